// round 10
// baseline (speedup 1.0000x reference)
#include <cuda_runtime.h>
#include <cuda_bf16.h>
#include <cstdint>

using bf16 = __nv_bfloat16;

#define SCALE 0.03125f  // D^-0.5, D=1024

// ---- scratch (device globals; allocation is forbidden) ----
__device__ bf16 g_xhi[8388608], g_xlo[8388608];        // x split [8192][1024]
__device__ bf16 g_whi[4194304], g_wlo[4194304];        // Wq,Wk,Wv,Wo split
__device__ bf16 g_qhi[25165824], g_qlo[25165824];      // q,k,v in [bh][n][d]
__device__ bf16 g_ohi[8388608], g_olo[8388608];        // attention out [8192][1024]
__device__ float g_bsum[4194304];                      // spatial+edge [16][512][512]

__device__ __forceinline__ void cp_async16(void* dst, const void* src) {
    uint32_t d = (uint32_t)__cvta_generic_to_shared(dst);
    asm volatile("cp.async.cg.shared.global [%0], [%1], 16;" :: "r"(d), "l"(src));
}
__device__ __forceinline__ void cp_commit() { asm volatile("cp.async.commit_group;"); }
__device__ __forceinline__ void cp_wait0()  { asm volatile("cp.async.wait_group 0;"); }
__device__ __forceinline__ void cp_wait1()  { asm volatile("cp.async.wait_group 1;"); }
__device__ __forceinline__ uint32_t ld_u32(const bf16* p) {
    return *reinterpret_cast<const uint32_t*>(p);
}
__device__ __forceinline__ void mma_bf16(float c[4], const uint32_t a[4], const uint32_t b[2]) {
    asm volatile(
        "mma.sync.aligned.m16n8k16.row.col.f32.bf16.bf16.f32 "
        "{%0,%1,%2,%3}, {%4,%5,%6,%7}, {%8,%9}, {%0,%1,%2,%3};"
        : "+f"(c[0]), "+f"(c[1]), "+f"(c[2]), "+f"(c[3])
        : "r"(a[0]), "r"(a[1]), "r"(a[2]), "r"(a[3]), "r"(b[0]), "r"(b[1]));
}
__device__ __forceinline__ void split2(float v, bf16& h, bf16& l) {
    h = __float2bfloat16(v);
    l = __float2bfloat16(v - __bfloat162float(h));
}

// ---- prep ----
__global__ void split_kernel(const float4* __restrict__ src, bf16* hi, bf16* lo, int n4) {
    int i = blockIdx.x * blockDim.x + threadIdx.x;
    if (i >= n4) return;
    float4 v = src[i];
    __nv_bfloat162 a, b, c, d;
    split2(v.x, a.x, c.x); split2(v.y, a.y, c.y);
    split2(v.z, b.x, d.x); split2(v.w, b.y, d.y);
    __nv_bfloat162* ph = reinterpret_cast<__nv_bfloat162*>(hi) + 2 * i;
    ph[0] = a; ph[1] = b;
    __nv_bfloat162* pl = reinterpret_cast<__nv_bfloat162*>(lo) + 2 * i;
    pl[0] = c; pl[1] = d;
}
__global__ void biassum_kernel(const float4* __restrict__ a, const float4* __restrict__ b, int n4) {
    int i = blockIdx.x * blockDim.x + threadIdx.x;
    if (i >= n4) return;
    float4 u = a[i], v = b[i];
    reinterpret_cast<float4*>(g_bsum)[i] =
        make_float4(u.x + v.x, u.y + v.y, u.z + v.z, u.w + v.w);
}

// ---- GEMM: C[M,N] = A[M,K] * W[N,K]^T, M=8192, N=K=1024 ----
#define GASTR 40
#define GEMM_SMEM (8 * 128 * GASTR * 2)

__device__ __forceinline__ void storeQKV(int z, int row, int col, float v0, float v1) {
    int b = row >> 9, n = row & 511, h = col >> 6, d = col & 63;
    size_t idx = (size_t)z * 8388608 + ((size_t)((b << 4) + h) * 512 + n) * 64 + d;
    __nv_bfloat162 hh, ll;
    split2(v0, hh.x, ll.x); split2(v1, hh.y, ll.y);
    *reinterpret_cast<__nv_bfloat162*>(g_qhi + idx) = hh;
    *reinterpret_cast<__nv_bfloat162*>(g_qlo + idx) = ll;
}

__global__ void __launch_bounds__(256, 1) gemm128(int mode, float* __restrict__ outF) {
    extern __shared__ bf16 sm[];
    const int tid = threadIdx.x, lane = tid & 31, warp = tid >> 5;
    const int wm = warp >> 2, wn = warp & 3;
    const int tm = blockIdx.y, tn = blockIdx.x, z = blockIdx.z;
    const bf16* Ahi = mode ? g_ohi : g_xhi;
    const bf16* Alo = mode ? g_olo : g_xlo;
    const int widx = mode ? 3 : z;
    const bf16* Bh = g_whi + (size_t)widx * 1048576;
    const bf16* Bl = g_wlo + (size_t)widx * 1048576;

    bf16* tiles[2][4];
    #pragma unroll
    for (int s = 0; s < 2; s++)
        #pragma unroll
        for (int t = 0; t < 4; t++) tiles[s][t] = sm + (size_t)(s * 4 + t) * (128 * GASTR);

    float acc[4][4][4] = {};
    const int c0 = tid & 3, lrow = tid >> 2;

    auto load_stage = [&](int st, int kt) {
        const int kOff = kt * 32 + c0 * 8;
        #pragma unroll
        for (int i = 0; i < 2; i++) {
            int row = lrow + i * 64;
            int sOff = row * GASTR + c0 * 8;
            size_t gA = (size_t)(tm * 128 + row) * 1024 + kOff;
            size_t gB = (size_t)(tn * 128 + row) * 1024 + kOff;
            cp_async16(tiles[st][0] + sOff, Ahi + gA);
            cp_async16(tiles[st][1] + sOff, Alo + gA);
            cp_async16(tiles[st][2] + sOff, Bh + gB);
            cp_async16(tiles[st][3] + sOff, Bl + gB);
        }
    };

    load_stage(0, 0); cp_commit();
    int st = 0;
    for (int kt = 0; kt < 32; kt++) {
        if (kt + 1 < 32) { load_stage(st ^ 1, kt + 1); cp_commit(); cp_wait1(); }
        else             { cp_wait0(); }
        __syncthreads();
        const bf16 *sAh = tiles[st][0], *sAl = tiles[st][1];
        const bf16 *sBh = tiles[st][2], *sBl = tiles[st][3];
        #pragma unroll
        for (int kk = 0; kk < 32; kk += 16) {
            const int k0 = kk + (lane & 3) * 2;
            uint32_t bh[4][2], bl[4][2];
            #pragma unroll
            for (int nt = 0; nt < 4; nt++) {
                int n = wn * 32 + nt * 8 + (lane >> 2);
                const bf16* p = sBh + n * GASTR + k0;
                bh[nt][0] = ld_u32(p); bh[nt][1] = ld_u32(p + 8);
                const bf16* q = sBl + n * GASTR + k0;
                bl[nt][0] = ld_u32(q); bl[nt][1] = ld_u32(q + 8);
            }
            #pragma unroll
            for (int mt = 0; mt < 4; mt++) {
                int r = wm * 64 + mt * 16 + (lane >> 2);
                const bf16* p = sAh + r * GASTR + k0;
                uint32_t ah[4] = { ld_u32(p), ld_u32(p + 8 * GASTR),
                                   ld_u32(p + 8), ld_u32(p + 8 * GASTR + 8) };
                const bf16* q = sAl + r * GASTR + k0;
                uint32_t al[4] = { ld_u32(q), ld_u32(q + 8 * GASTR),
                                   ld_u32(q + 8), ld_u32(q + 8 * GASTR + 8) };
                #pragma unroll
                for (int nt = 0; nt < 4; nt++) {
                    mma_bf16(acc[mt][nt], ah, bh[nt]);
                    mma_bf16(acc[mt][nt], ah, bl[nt]);
                    mma_bf16(acc[mt][nt], al, bh[nt]);
                }
            }
        }
        __syncthreads();
        st ^= 1;
    }
    #pragma unroll
    for (int mt = 0; mt < 4; mt++)
        #pragma unroll
        for (int nt = 0; nt < 4; nt++) {
            int r0 = tm * 128 + wm * 64 + mt * 16 + (lane >> 2);
            int cc = tn * 128 + wn * 32 + nt * 8 + (lane & 3) * 2;
            if (mode == 0) {
                storeQKV(z, r0, cc, acc[mt][nt][0], acc[mt][nt][1]);
                storeQKV(z, r0 + 8, cc, acc[mt][nt][2], acc[mt][nt][3]);
            } else {
                *reinterpret_cast<float2*>(outF + (size_t)r0 * 1024 + cc) =
                    make_float2(acc[mt][nt][0], acc[mt][nt][1]);
                *reinterpret_cast<float2*>(outF + (size_t)(r0 + 8) * 1024 + cc) =
                    make_float2(acc[mt][nt][2], acc[mt][nt][3]);
            }
        }
}

// ---- fused attention: CTA = (b*16+h, 32 query rows) ----
#define QSTR 72
#define KSTR 72
#define VSTR 136
#define SSTR 516
#define PSTR 520
#define OFF_P_HI 66048
#define OFF_P_LO 99328
#define OFF_Q_HI 132608
#define OFF_Q_LO 137216
#define OFF_KV_HI 141824
#define OFF_KV_LO 160256
#define ATTN_SMEM 178688

__global__ void __launch_bounds__(256, 1) attn_kernel() {
    extern __shared__ char smc[];
    float* Ss = reinterpret_cast<float*>(smc);
    bf16* Phi = reinterpret_cast<bf16*>(smc + OFF_P_HI);
    bf16* Plo = reinterpret_cast<bf16*>(smc + OFF_P_LO);
    bf16* Qh  = reinterpret_cast<bf16*>(smc + OFF_Q_HI);
    bf16* Ql  = reinterpret_cast<bf16*>(smc + OFF_Q_LO);
    bf16* KVh = reinterpret_cast<bf16*>(smc + OFF_KV_HI);
    bf16* KVl = reinterpret_cast<bf16*>(smc + OFF_KV_LO);

    const int tid = threadIdx.x, lane = tid & 31, warp = tid >> 5;
    const int wm = warp >> 2, wn = warp & 3;
    const int bh = blockIdx.x, rb = blockIdx.y;
    const size_t baseQ = (size_t)bh * 32768 + (size_t)rb * 2048;
    const size_t baseK = 8388608u + (size_t)bh * 32768;
    const size_t baseV = 16777216u + (size_t)bh * 32768;

    { // Q tile 32x64
        int row = tid >> 3, seg = (tid & 7) * 8;
        *reinterpret_cast<uint4*>(Qh + row * QSTR + seg) =
            *reinterpret_cast<const uint4*>(g_qhi + baseQ + row * 64 + seg);
        *reinterpret_cast<uint4*>(Ql + row * QSTR + seg) =
            *reinterpret_cast<const uint4*>(g_qlo + baseQ + row * 64 + seg);
    }
    const float* bs = g_bsum + ((size_t)(bh >> 4) * 512 + (size_t)rb * 32) * 512;

    // phase 1: S = scale*(Q K^T) + bias
    for (int kb = 0; kb < 4; kb++) {
        #pragma unroll
        for (int i = 0; i < 4; i++) {
            int c = tid + i * 256;
            int row = c >> 3, seg = (c & 7) * 8;
            *reinterpret_cast<uint4*>(KVh + row * KSTR + seg) =
                *reinterpret_cast<const uint4*>(g_qhi + baseK + (size_t)(kb * 128 + row) * 64 + seg);
            *reinterpret_cast<uint4*>(KVl + row * KSTR + seg) =
                *reinterpret_cast<const uint4*>(g_qlo + baseK + (size_t)(kb * 128 + row) * 64 + seg);
        }
        __syncthreads();
        float acc[4][4] = {};
        #pragma unroll
        for (int kk = 0; kk < 64; kk += 16) {
            const int k0 = kk + (lane & 3) * 2;
            const int r = wm * 16 + (lane >> 2);
            const bf16* pa = Qh + r * QSTR + k0;
            uint32_t ah[4] = { ld_u32(pa), ld_u32(pa + 8 * QSTR),
                               ld_u32(pa + 8), ld_u32(pa + 8 * QSTR + 8) };
            const bf16* pl = Ql + r * QSTR + k0;
            uint32_t al[4] = { ld_u32(pl), ld_u32(pl + 8 * QSTR),
                               ld_u32(pl + 8), ld_u32(pl + 8 * QSTR + 8) };
            #pragma unroll
            for (int nt = 0; nt < 4; nt++) {
                int n = wn * 32 + nt * 8 + (lane >> 2);
                const bf16* pb = KVh + n * KSTR + k0;
                uint32_t bhf[2] = { ld_u32(pb), ld_u32(pb + 8) };
                const bf16* pc = KVl + n * KSTR + k0;
                uint32_t blf[2] = { ld_u32(pc), ld_u32(pc + 8) };
                mma_bf16(acc[nt], ah, bhf);
                mma_bf16(acc[nt], ah, blf);
                mma_bf16(acc[nt], al, bhf);
            }
        }
        int qr = wm * 16 + (lane >> 2);
        #pragma unroll
        for (int nt = 0; nt < 4; nt++) {
            int key = kb * 128 + wn * 32 + nt * 8 + (lane & 3) * 2;
            Ss[qr * SSTR + key]           = acc[nt][0] * SCALE + bs[qr * 512 + key];
            Ss[qr * SSTR + key + 1]       = acc[nt][1] * SCALE + bs[qr * 512 + key + 1];
            Ss[(qr + 8) * SSTR + key]     = acc[nt][2] * SCALE + bs[(qr + 8) * 512 + key];
            Ss[(qr + 8) * SSTR + key + 1] = acc[nt][3] * SCALE + bs[(qr + 8) * 512 + key + 1];
        }
        __syncthreads();
    }

    // phase 2: row softmax with all-zero-row masking
    #pragma unroll
    for (int rr = 0; rr < 4; rr++) {
        int r = warp * 4 + rr;
        float v[16], mx = -3.0e38f;
        bool nz = false;
        #pragma unroll
        for (int j = 0; j < 16; j++) {
            v[j] = Ss[r * SSTR + lane + j * 32];
            nz |= (v[j] != 0.0f);
            mx = fmaxf(mx, v[j]);
        }
        #pragma unroll
        for (int o = 16; o > 0; o >>= 1) mx = fmaxf(mx, __shfl_xor_sync(~0u, mx, o));
        bool rowNz = __any_sync(~0u, nz);
        float s = 0.f;
        #pragma unroll
        for (int j = 0; j < 16; j++) { v[j] = __expf(v[j] - mx); s += v[j]; }
        #pragma unroll
        for (int o = 16; o > 0; o >>= 1) s += __shfl_xor_sync(~0u, s, o);
        float inv = rowNz ? (1.0f / s) : 0.0f;
        #pragma unroll
        for (int j = 0; j < 16; j++) {
            bf16 h, l;
            split2(v[j] * inv, h, l);
            Phi[r * PSTR + lane + j * 32] = h;
            Plo[r * PSTR + lane + j * 32] = l;
        }
    }

    // phase 3: O = P V, V transposed in smem as [d][m]
    float ao[2][4] = {};
    for (int vb = 0; vb < 4; vb++) {
        __syncthreads();
        #pragma unroll
        for (int i = 0; i < 16; i++) {
            int id = tid + i * 256;
            int m = id >> 5, dd = (id & 31) * 2;
            __nv_bfloat162 w2 = *reinterpret_cast<const __nv_bfloat162*>(
                g_qhi + baseV + (size_t)(vb * 128 + m) * 64 + dd);
            KVh[dd * VSTR + m] = w2.x; KVh[(dd + 1) * VSTR + m] = w2.y;
            __nv_bfloat162 w3 = *reinterpret_cast<const __nv_bfloat162*>(
                g_qlo + baseV + (size_t)(vb * 128 + m) * 64 + dd);
            KVl[dd * VSTR + m] = w3.x; KVl[(dd + 1) * VSTR + m] = w3.y;
        }
        __syncthreads();
        #pragma unroll
        for (int kk = 0; kk < 128; kk += 16) {
            const int kg = vb * 128 + kk;
            const int cp = (lane & 3) * 2;
            const int r = wm * 16 + (lane >> 2);
            const bf16* pa = Phi + r * PSTR + kg + cp;
            uint32_t ah[4] = { ld_u32(pa), ld_u32(pa + 8 * PSTR),
                               ld_u32(pa + 8), ld_u32(pa + 8 * PSTR + 8) };
            const bf16* pl = Plo + r * PSTR + kg + cp;
            uint32_t al[4] = { ld_u32(pl), ld_u32(pl + 8 * PSTR),
                               ld_u32(pl + 8), ld_u32(pl + 8 * PSTR + 8) };
            #pragma unroll
            for (int nt = 0; nt < 2; nt++) {
                int n = wn * 16 + nt * 8 + (lane >> 2);
                const bf16* pb = KVh + n * VSTR + kk + cp;
                uint32_t bhf[2] = { ld_u32(pb), ld_u32(pb + 8) };
                const bf16* pc = KVl + n * VSTR + kk + cp;
                uint32_t blf[2] = { ld_u32(pc), ld_u32(pc + 8) };
                mma_bf16(ao[nt], ah, bhf);
                mma_bf16(ao[nt], ah, blf);
                mma_bf16(ao[nt], al, bhf);
            }
        }
    }

    // epilogue: [b*512+q][h*64+d] hi/lo
    {
        int b = bh >> 4, h = bh & 15;
        int q0 = rb * 32 + wm * 16 + (lane >> 2);
        #pragma unroll
        for (int nt = 0; nt < 2; nt++) {
            int col = h * 64 + wn * 16 + nt * 8 + (lane & 3) * 2;
            size_t idx0 = (size_t)(b * 512 + q0) * 1024 + col;
            __nv_bfloat162 hh, ll;
            split2(ao[nt][0], hh.x, ll.x); split2(ao[nt][1], hh.y, ll.y);
            *reinterpret_cast<__nv_bfloat162*>(g_ohi + idx0) = hh;
            *reinterpret_cast<__nv_bfloat162*>(g_olo + idx0) = ll;
            split2(ao[nt][2], hh.x, ll.x); split2(ao[nt][3], hh.y, ll.y);
            *reinterpret_cast<__nv_bfloat162*>(g_ohi + idx0 + 8192) = hh;
            *reinterpret_cast<__nv_bfloat162*>(g_olo + idx0 + 8192) = ll;
        }
    }
}

extern "C" void kernel_launch(void* const* d_in, const int* in_sizes, int n_in,
                              void* d_out, int out_size) {
    const float* x  = (const float*)d_in[0];
    const float* sp = (const float*)d_in[1];
    const float* ed = (const float*)d_in[2];

    cudaFuncSetAttribute(gemm128, cudaFuncAttributeMaxDynamicSharedMemorySize, GEMM_SMEM);
    cudaFuncSetAttribute(attn_kernel, cudaFuncAttributeMaxDynamicSharedMemorySize, ATTN_SMEM);

    bf16 *xhi, *xlo, *whi, *wlo;
    cudaGetSymbolAddress((void**)&xhi, g_xhi);
    cudaGetSymbolAddress((void**)&xlo, g_xlo);
    cudaGetSymbolAddress((void**)&whi, g_whi);
    cudaGetSymbolAddress((void**)&wlo, g_wlo);

    // split x and weights
    split_kernel<<<8192, 256>>>((const float4*)x, xhi, xlo, 2097152);
    for (int i = 0; i < 4; i++)
        split_kernel<<<1024, 256>>>((const float4*)d_in[3 + i],
                                    whi + (size_t)i * 1048576,
                                    wlo + (size_t)i * 1048576, 262144);
    // bias = spatial + edge
    biassum_kernel<<<4096, 256>>>((const float4*)sp, (const float4*)ed, 1048576);

    // QKV projections
    gemm128<<<dim3(8, 64, 3), 256, GEMM_SMEM>>>(0, nullptr);
    // fused attention
    attn_kernel<<<dim3(256, 16), 256, ATTN_SMEM>>>();
    // output projection -> d_out (fp32)
    gemm128<<<dim3(8, 64, 1), 256, GEMM_SMEM>>>(1, (float*)d_out);
}

// round 11
// speedup vs baseline: 1.0009x; 1.0009x over previous
#include <cuda_runtime.h>
#include <cuda_bf16.h>
#include <cstdint>

using bf16 = __nv_bfloat16;

#define SCALE 0.03125f  // D^-0.5, D=1024

// ---- scratch (device globals; allocation is forbidden) ----
__device__ bf16 g_xhi[8388608], g_xlo[8388608];        // x split [8192][1024]
__device__ bf16 g_whi[4194304], g_wlo[4194304];        // Wq,Wk,Wv,Wo split
__device__ bf16 g_qhi[25165824], g_qlo[25165824];      // q,k,v in [bh][n][d]
__device__ bf16 g_ohi[8388608], g_olo[8388608];        // attention out [8192][1024]
__device__ float g_bsum[4194304];                      // spatial+edge [16][512][512]

__device__ __forceinline__ void cp_async16(void* dst, const void* src) {
    uint32_t d = (uint32_t)__cvta_generic_to_shared(dst);
    asm volatile("cp.async.cg.shared.global [%0], [%1], 16;" :: "r"(d), "l"(src));
}
__device__ __forceinline__ void cp_commit() { asm volatile("cp.async.commit_group;"); }
__device__ __forceinline__ void cp_wait0()  { asm volatile("cp.async.wait_group 0;"); }
__device__ __forceinline__ void cp_wait1()  { asm volatile("cp.async.wait_group 1;"); }
__device__ __forceinline__ uint32_t ld_u32(const bf16* p) {
    return *reinterpret_cast<const uint32_t*>(p);
}
__device__ __forceinline__ void mma_bf16(float c[4], const uint32_t a[4], const uint32_t b[2]) {
    asm volatile(
        "mma.sync.aligned.m16n8k16.row.col.f32.bf16.bf16.f32 "
        "{%0,%1,%2,%3}, {%4,%5,%6,%7}, {%8,%9}, {%0,%1,%2,%3};"
        : "+f"(c[0]), "+f"(c[1]), "+f"(c[2]), "+f"(c[3])
        : "r"(a[0]), "r"(a[1]), "r"(a[2]), "r"(a[3]), "r"(b[0]), "r"(b[1]));
}
__device__ __forceinline__ void split2(float v, bf16& h, bf16& l) {
    h = __float2bfloat16(v);
    l = __float2bfloat16(v - __bfloat162float(h));
}

// ---- prep ----
__global__ void split_kernel(const float4* __restrict__ src, bf16* hi, bf16* lo, int n4) {
    int i = blockIdx.x * blockDim.x + threadIdx.x;
    if (i >= n4) return;
    float4 v = src[i];
    __nv_bfloat162 a, b, c, d;
    split2(v.x, a.x, c.x); split2(v.y, a.y, c.y);
    split2(v.z, b.x, d.x); split2(v.w, b.y, d.y);
    __nv_bfloat162* ph = reinterpret_cast<__nv_bfloat162*>(hi) + 2 * i;
    ph[0] = a; ph[1] = b;
    __nv_bfloat162* pl = reinterpret_cast<__nv_bfloat162*>(lo) + 2 * i;
    pl[0] = c; pl[1] = d;
}
__global__ void biassum_kernel(const float4* __restrict__ a, const float4* __restrict__ b, int n4) {
    int i = blockIdx.x * blockDim.x + threadIdx.x;
    if (i >= n4) return;
    float4 u = a[i], v = b[i];
    reinterpret_cast<float4*>(g_bsum)[i] =
        make_float4(u.x + v.x, u.y + v.y, u.z + v.z, u.w + v.w);
}

// ---- GEMM: C[M,N] = A[M,K] * W[N,K]^T, M=8192, N=K=1024 ----
#define GASTR 40
#define GEMM_SMEM (8 * 128 * GASTR * 2)

__device__ __forceinline__ void storeQKV(int z, int row, int col, float v0, float v1) {
    int b = row >> 9, n = row & 511, h = col >> 6, d = col & 63;
    size_t idx = (size_t)z * 8388608 + ((size_t)((b << 4) + h) * 512 + n) * 64 + d;
    __nv_bfloat162 hh, ll;
    split2(v0, hh.x, ll.x); split2(v1, hh.y, ll.y);
    *reinterpret_cast<__nv_bfloat162*>(g_qhi + idx) = hh;
    *reinterpret_cast<__nv_bfloat162*>(g_qlo + idx) = ll;
}

__global__ void __launch_bounds__(256, 1) gemm128(int mode, float* __restrict__ outF) {
    extern __shared__ bf16 sm[];
    const int tid = threadIdx.x, lane = tid & 31, warp = tid >> 5;
    const int wm = warp >> 2, wn = warp & 3;
    const int tm = blockIdx.y, tn = blockIdx.x, z = blockIdx.z;
    const bf16* Ahi = mode ? g_ohi : g_xhi;
    const bf16* Alo = mode ? g_olo : g_xlo;
    const int widx = mode ? 3 : z;
    const bf16* Bh = g_whi + (size_t)widx * 1048576;
    const bf16* Bl = g_wlo + (size_t)widx * 1048576;

    bf16* tiles[2][4];
    #pragma unroll
    for (int s = 0; s < 2; s++)
        #pragma unroll
        for (int t = 0; t < 4; t++) tiles[s][t] = sm + (size_t)(s * 4 + t) * (128 * GASTR);

    float acc[4][4][4] = {};
    const int c0 = tid & 3, lrow = tid >> 2;

    auto load_stage = [&](int st, int kt) {
        const int kOff = kt * 32 + c0 * 8;
        #pragma unroll
        for (int i = 0; i < 2; i++) {
            int row = lrow + i * 64;
            int sOff = row * GASTR + c0 * 8;
            size_t gA = (size_t)(tm * 128 + row) * 1024 + kOff;
            size_t gB = (size_t)(tn * 128 + row) * 1024 + kOff;
            cp_async16(tiles[st][0] + sOff, Ahi + gA);
            cp_async16(tiles[st][1] + sOff, Alo + gA);
            cp_async16(tiles[st][2] + sOff, Bh + gB);
            cp_async16(tiles[st][3] + sOff, Bl + gB);
        }
    };

    load_stage(0, 0); cp_commit();
    int st = 0;
    for (int kt = 0; kt < 32; kt++) {
        if (kt + 1 < 32) { load_stage(st ^ 1, kt + 1); cp_commit(); cp_wait1(); }
        else             { cp_wait0(); }
        __syncthreads();
        const bf16 *sAh = tiles[st][0], *sAl = tiles[st][1];
        const bf16 *sBh = tiles[st][2], *sBl = tiles[st][3];
        #pragma unroll
        for (int kk = 0; kk < 32; kk += 16) {
            const int k0 = kk + (lane & 3) * 2;
            uint32_t bh[4][2], bl[4][2];
            #pragma unroll
            for (int nt = 0; nt < 4; nt++) {
                int n = wn * 32 + nt * 8 + (lane >> 2);
                const bf16* p = sBh + n * GASTR + k0;
                bh[nt][0] = ld_u32(p); bh[nt][1] = ld_u32(p + 8);
                const bf16* q = sBl + n * GASTR + k0;
                bl[nt][0] = ld_u32(q); bl[nt][1] = ld_u32(q + 8);
            }
            #pragma unroll
            for (int mt = 0; mt < 4; mt++) {
                int r = wm * 64 + mt * 16 + (lane >> 2);
                const bf16* p = sAh + r * GASTR + k0;
                uint32_t ah[4] = { ld_u32(p), ld_u32(p + 8 * GASTR),
                                   ld_u32(p + 8), ld_u32(p + 8 * GASTR + 8) };
                const bf16* q = sAl + r * GASTR + k0;
                uint32_t al[4] = { ld_u32(q), ld_u32(q + 8 * GASTR),
                                   ld_u32(q + 8), ld_u32(q + 8 * GASTR + 8) };
                #pragma unroll
                for (int nt = 0; nt < 4; nt++) {
                    mma_bf16(acc[mt][nt], ah, bh[nt]);
                    mma_bf16(acc[mt][nt], ah, bl[nt]);
                    mma_bf16(acc[mt][nt], al, bh[nt]);
                }
            }
        }
        __syncthreads();
        st ^= 1;
    }
    #pragma unroll
    for (int mt = 0; mt < 4; mt++)
        #pragma unroll
        for (int nt = 0; nt < 4; nt++) {
            int r0 = tm * 128 + wm * 64 + mt * 16 + (lane >> 2);
            int cc = tn * 128 + wn * 32 + nt * 8 + (lane & 3) * 2;
            if (mode == 0) {
                storeQKV(z, r0, cc, acc[mt][nt][0], acc[mt][nt][1]);
                storeQKV(z, r0 + 8, cc, acc[mt][nt][2], acc[mt][nt][3]);
            } else {
                *reinterpret_cast<float2*>(outF + (size_t)r0 * 1024 + cc) =
                    make_float2(acc[mt][nt][0], acc[mt][nt][1]);
                *reinterpret_cast<float2*>(outF + (size_t)(r0 + 8) * 1024 + cc) =
                    make_float2(acc[mt][nt][2], acc[mt][nt][3]);
            }
        }
}

// ---- fused attention: CTA = (b*16+h, 32 query rows) ----
#define QSTR 72
#define KSTR 72
#define VSTR 136
#define SSTR 516
#define PSTR 520
#define OFF_P_HI 66048
#define OFF_P_LO 99328
#define OFF_Q_HI 132608
#define OFF_Q_LO 137216
#define OFF_KV_HI 141824
#define OFF_KV_LO 160256
#define ATTN_SMEM 178688

__global__ void __launch_bounds__(256, 1) attn_kernel() {
    extern __shared__ char smc[];
    float* Ss = reinterpret_cast<float*>(smc);
    bf16* Phi = reinterpret_cast<bf16*>(smc + OFF_P_HI);
    bf16* Plo = reinterpret_cast<bf16*>(smc + OFF_P_LO);
    bf16* Qh  = reinterpret_cast<bf16*>(smc + OFF_Q_HI);
    bf16* Ql  = reinterpret_cast<bf16*>(smc + OFF_Q_LO);
    bf16* KVh = reinterpret_cast<bf16*>(smc + OFF_KV_HI);
    bf16* KVl = reinterpret_cast<bf16*>(smc + OFF_KV_LO);

    const int tid = threadIdx.x, lane = tid & 31, warp = tid >> 5;
    const int wm = warp >> 2, wn = warp & 3;
    const int bh = blockIdx.x, rb = blockIdx.y;
    const size_t baseQ = (size_t)bh * 32768 + (size_t)rb * 2048;
    const size_t baseK = 8388608u + (size_t)bh * 32768;
    const size_t baseV = 16777216u + (size_t)bh * 32768;

    { // Q tile 32x64
        int row = tid >> 3, seg = (tid & 7) * 8;
        *reinterpret_cast<uint4*>(Qh + row * QSTR + seg) =
            *reinterpret_cast<const uint4*>(g_qhi + baseQ + row * 64 + seg);
        *reinterpret_cast<uint4*>(Ql + row * QSTR + seg) =
            *reinterpret_cast<const uint4*>(g_qlo + baseQ + row * 64 + seg);
    }
    const float* bs = g_bsum + ((size_t)(bh >> 4) * 512 + (size_t)rb * 32) * 512;

    // phase 1: S = scale*(Q K^T) + bias
    for (int kb = 0; kb < 4; kb++) {
        #pragma unroll
        for (int i = 0; i < 4; i++) {
            int c = tid + i * 256;
            int row = c >> 3, seg = (c & 7) * 8;
            *reinterpret_cast<uint4*>(KVh + row * KSTR + seg) =
                *reinterpret_cast<const uint4*>(g_qhi + baseK + (size_t)(kb * 128 + row) * 64 + seg);
            *reinterpret_cast<uint4*>(KVl + row * KSTR + seg) =
                *reinterpret_cast<const uint4*>(g_qlo + baseK + (size_t)(kb * 128 + row) * 64 + seg);
        }
        __syncthreads();
        float acc[4][4] = {};
        #pragma unroll
        for (int kk = 0; kk < 64; kk += 16) {
            const int k0 = kk + (lane & 3) * 2;
            const int r = wm * 16 + (lane >> 2);
            const bf16* pa = Qh + r * QSTR + k0;
            uint32_t ah[4] = { ld_u32(pa), ld_u32(pa + 8 * QSTR),
                               ld_u32(pa + 8), ld_u32(pa + 8 * QSTR + 8) };
            const bf16* pl = Ql + r * QSTR + k0;
            uint32_t al[4] = { ld_u32(pl), ld_u32(pl + 8 * QSTR),
                               ld_u32(pl + 8), ld_u32(pl + 8 * QSTR + 8) };
            #pragma unroll
            for (int nt = 0; nt < 4; nt++) {
                int n = wn * 32 + nt * 8 + (lane >> 2);
                const bf16* pb = KVh + n * KSTR + k0;
                uint32_t bhf[2] = { ld_u32(pb), ld_u32(pb + 8) };
                const bf16* pc = KVl + n * KSTR + k0;
                uint32_t blf[2] = { ld_u32(pc), ld_u32(pc + 8) };
                mma_bf16(acc[nt], ah, bhf);
                mma_bf16(acc[nt], ah, blf);
                mma_bf16(acc[nt], al, bhf);
            }
        }
        int qr = wm * 16 + (lane >> 2);
        #pragma unroll
        for (int nt = 0; nt < 4; nt++) {
            int key = kb * 128 + wn * 32 + nt * 8 + (lane & 3) * 2;
            Ss[qr * SSTR + key]           = acc[nt][0] * SCALE + bs[qr * 512 + key];
            Ss[qr * SSTR + key + 1]       = acc[nt][1] * SCALE + bs[qr * 512 + key + 1];
            Ss[(qr + 8) * SSTR + key]     = acc[nt][2] * SCALE + bs[(qr + 8) * 512 + key];
            Ss[(qr + 8) * SSTR + key + 1] = acc[nt][3] * SCALE + bs[(qr + 8) * 512 + key + 1];
        }
        __syncthreads();
    }

    // phase 2: row softmax with all-zero-row masking
    #pragma unroll
    for (int rr = 0; rr < 4; rr++) {
        int r = warp * 4 + rr;
        float v[16], mx = -3.0e38f;
        bool nz = false;
        #pragma unroll
        for (int j = 0; j < 16; j++) {
            v[j] = Ss[r * SSTR + lane + j * 32];
            nz |= (v[j] != 0.0f);
            mx = fmaxf(mx, v[j]);
        }
        #pragma unroll
        for (int o = 16; o > 0; o >>= 1) mx = fmaxf(mx, __shfl_xor_sync(~0u, mx, o));
        bool rowNz = __any_sync(~0u, nz);
        float s = 0.f;
        #pragma unroll
        for (int j = 0; j < 16; j++) { v[j] = __expf(v[j] - mx); s += v[j]; }
        #pragma unroll
        for (int o = 16; o > 0; o >>= 1) s += __shfl_xor_sync(~0u, s, o);
        float inv = rowNz ? (1.0f / s) : 0.0f;
        #pragma unroll
        for (int j = 0; j < 16; j++) {
            bf16 h, l;
            split2(v[j] * inv, h, l);
            Phi[r * PSTR + lane + j * 32] = h;
            Plo[r * PSTR + lane + j * 32] = l;
        }
    }

    // phase 3: O = P V, V transposed in smem as [d][m]
    float ao[2][4] = {};
    for (int vb = 0; vb < 4; vb++) {
        __syncthreads();
        #pragma unroll
        for (int i = 0; i < 16; i++) {
            int id = tid + i * 256;
            int m = id >> 5, dd = (id & 31) * 2;
            __nv_bfloat162 w2 = *reinterpret_cast<const __nv_bfloat162*>(
                g_qhi + baseV + (size_t)(vb * 128 + m) * 64 + dd);
            KVh[dd * VSTR + m] = w2.x; KVh[(dd + 1) * VSTR + m] = w2.y;
            __nv_bfloat162 w3 = *reinterpret_cast<const __nv_bfloat162*>(
                g_qlo + baseV + (size_t)(vb * 128 + m) * 64 + dd);
            KVl[dd * VSTR + m] = w3.x; KVl[(dd + 1) * VSTR + m] = w3.y;
        }
        __syncthreads();
        #pragma unroll
        for (int kk = 0; kk < 128; kk += 16) {
            const int kg = vb * 128 + kk;
            const int cp = (lane & 3) * 2;
            const int r = wm * 16 + (lane >> 2);
            const bf16* pa = Phi + r * PSTR + kg + cp;
            uint32_t ah[4] = { ld_u32(pa), ld_u32(pa + 8 * PSTR),
                               ld_u32(pa + 8), ld_u32(pa + 8 * PSTR + 8) };
            const bf16* pl = Plo + r * PSTR + kg + cp;
            uint32_t al[4] = { ld_u32(pl), ld_u32(pl + 8 * PSTR),
                               ld_u32(pl + 8), ld_u32(pl + 8 * PSTR + 8) };
            #pragma unroll
            for (int nt = 0; nt < 2; nt++) {
                int n = wn * 16 + nt * 8 + (lane >> 2);
                const bf16* pb = KVh + n * VSTR + kk + cp;
                uint32_t bhf[2] = { ld_u32(pb), ld_u32(pb + 8) };
                const bf16* pc = KVl + n * VSTR + kk + cp;
                uint32_t blf[2] = { ld_u32(pc), ld_u32(pc + 8) };
                mma_bf16(ao[nt], ah, bhf);
                mma_bf16(ao[nt], ah, blf);
                mma_bf16(ao[nt], al, bhf);
            }
        }
    }

    // epilogue: [b*512+q][h*64+d] hi/lo
    {
        int b = bh >> 4, h = bh & 15;
        int q0 = rb * 32 + wm * 16 + (lane >> 2);
        #pragma unroll
        for (int nt = 0; nt < 2; nt++) {
            int col = h * 64 + wn * 16 + nt * 8 + (lane & 3) * 2;
            size_t idx0 = (size_t)(b * 512 + q0) * 1024 + col;
            __nv_bfloat162 hh, ll;
            split2(ao[nt][0], hh.x, ll.x); split2(ao[nt][1], hh.y, ll.y);
            *reinterpret_cast<__nv_bfloat162*>(g_ohi + idx0) = hh;
            *reinterpret_cast<__nv_bfloat162*>(g_olo + idx0) = ll;
            split2(ao[nt][2], hh.x, ll.x); split2(ao[nt][3], hh.y, ll.y);
            *reinterpret_cast<__nv_bfloat162*>(g_ohi + idx0 + 8192) = hh;
            *reinterpret_cast<__nv_bfloat162*>(g_olo + idx0 + 8192) = ll;
        }
    }
}

extern "C" void kernel_launch(void* const* d_in, const int* in_sizes, int n_in,
                              void* d_out, int out_size) {
    const float* x  = (const float*)d_in[0];
    const float* sp = (const float*)d_in[1];
    const float* ed = (const float*)d_in[2];

    cudaFuncSetAttribute(gemm128, cudaFuncAttributeMaxDynamicSharedMemorySize, GEMM_SMEM);
    cudaFuncSetAttribute(attn_kernel, cudaFuncAttributeMaxDynamicSharedMemorySize, ATTN_SMEM);

    bf16 *xhi, *xlo, *whi, *wlo;
    cudaGetSymbolAddress((void**)&xhi, g_xhi);
    cudaGetSymbolAddress((void**)&xlo, g_xlo);
    cudaGetSymbolAddress((void**)&whi, g_whi);
    cudaGetSymbolAddress((void**)&wlo, g_wlo);

    // split x and weights
    split_kernel<<<8192, 256>>>((const float4*)x, xhi, xlo, 2097152);
    for (int i = 0; i < 4; i++)
        split_kernel<<<1024, 256>>>((const float4*)d_in[3 + i],
                                    whi + (size_t)i * 1048576,
                                    wlo + (size_t)i * 1048576, 262144);
    // bias = spatial + edge
    biassum_kernel<<<4096, 256>>>((const float4*)sp, (const float4*)ed, 1048576);

    // QKV projections
    gemm128<<<dim3(8, 64, 3), 256, GEMM_SMEM>>>(0, nullptr);
    // fused attention
    attn_kernel<<<dim3(256, 16), 256, ATTN_SMEM>>>();
    // output projection -> d_out (fp32)
    gemm128<<<dim3(8, 64, 1), 256, GEMM_SMEM>>>(1, (float*)d_out);
}

// round 12
// speedup vs baseline: 1.5227x; 1.5213x over previous
#include <cuda_runtime.h>
#include <cuda_bf16.h>
#include <cstdint>

using bf16 = __nv_bfloat16;

#define SCALE 0.03125f  // D^-0.5, D=1024

// ---- scratch (device globals; allocation is forbidden) ----
__device__ bf16 g_xhi[8388608], g_xlo[8388608];        // x split [8192][1024]
__device__ bf16 g_whi[4194304], g_wlo[4194304];        // Wq,Wk,Wv,Wo split
__device__ bf16 g_qhi[25165824], g_qlo[25165824];      // q,k,v in [bh][n][d]
__device__ bf16 g_ohi[8388608], g_olo[8388608];        // attention out [8192][1024]
__device__ float g_bsum[4194304];                      // spatial+edge [16][512][512]

__device__ __forceinline__ void cp_async16(void* dst, const void* src) {
    uint32_t d = (uint32_t)__cvta_generic_to_shared(dst);
    asm volatile("cp.async.cg.shared.global [%0], [%1], 16;" :: "r"(d), "l"(src));
}
__device__ __forceinline__ void cp_commit() { asm volatile("cp.async.commit_group;"); }
__device__ __forceinline__ void cp_wait0()  { asm volatile("cp.async.wait_group 0;"); }
__device__ __forceinline__ void cp_wait1()  { asm volatile("cp.async.wait_group 1;"); }

__device__ __forceinline__ void ldsm4(uint32_t r[4], const bf16* p) {
    uint32_t a = (uint32_t)__cvta_generic_to_shared(p);
    asm volatile("ldmatrix.sync.aligned.m8n8.x4.shared.b16 {%0,%1,%2,%3}, [%4];"
                 : "=r"(r[0]), "=r"(r[1]), "=r"(r[2]), "=r"(r[3]) : "r"(a));
}
__device__ __forceinline__ void ldsm4t(uint32_t r[4], const bf16* p) {
    uint32_t a = (uint32_t)__cvta_generic_to_shared(p);
    asm volatile("ldmatrix.sync.aligned.m8n8.x4.trans.shared.b16 {%0,%1,%2,%3}, [%4];"
                 : "=r"(r[0]), "=r"(r[1]), "=r"(r[2]), "=r"(r[3]) : "r"(a));
}
__device__ __forceinline__ void mma_bf16(float c[4], const uint32_t a[4], const uint32_t b[2]) {
    asm volatile(
        "mma.sync.aligned.m16n8k16.row.col.f32.bf16.bf16.f32 "
        "{%0,%1,%2,%3}, {%4,%5,%6,%7}, {%8,%9}, {%0,%1,%2,%3};"
        : "+f"(c[0]), "+f"(c[1]), "+f"(c[2]), "+f"(c[3])
        : "r"(a[0]), "r"(a[1]), "r"(a[2]), "r"(a[3]), "r"(b[0]), "r"(b[1]));
}
__device__ __forceinline__ void split2(float v, bf16& h, bf16& l) {
    h = __float2bfloat16(v);
    l = __float2bfloat16(v - __bfloat162float(h));
}

// ---- prep ----
__global__ void split_kernel(const float4* __restrict__ src, bf16* hi, bf16* lo, int n4) {
    int i = blockIdx.x * blockDim.x + threadIdx.x;
    if (i >= n4) return;
    float4 v = src[i];
    __nv_bfloat162 a, b, c, d;
    split2(v.x, a.x, c.x); split2(v.y, a.y, c.y);
    split2(v.z, b.x, d.x); split2(v.w, b.y, d.y);
    __nv_bfloat162* ph = reinterpret_cast<__nv_bfloat162*>(hi) + 2 * i;
    ph[0] = a; ph[1] = b;
    __nv_bfloat162* pl = reinterpret_cast<__nv_bfloat162*>(lo) + 2 * i;
    pl[0] = c; pl[1] = d;
}
// all four weights in one launch (blockIdx.y selects the weight)
__global__ void split_w_kernel(const float4* __restrict__ w0, const float4* __restrict__ w1,
                               const float4* __restrict__ w2, const float4* __restrict__ w3) {
    int y = blockIdx.y;
    const float4* src = (y == 0) ? w0 : (y == 1) ? w1 : (y == 2) ? w2 : w3;
    int i = blockIdx.x * blockDim.x + threadIdx.x;   // 0..262143
    float4 v = src[i];
    __nv_bfloat162 a, b, c, d;
    split2(v.x, a.x, c.x); split2(v.y, a.y, c.y);
    split2(v.z, b.x, d.x); split2(v.w, b.y, d.y);
    size_t base = (size_t)y * 524288 + 2 * (size_t)i;
    __nv_bfloat162* ph = reinterpret_cast<__nv_bfloat162*>(g_whi) + base;
    ph[0] = a; ph[1] = b;
    __nv_bfloat162* pl = reinterpret_cast<__nv_bfloat162*>(g_wlo) + base;
    pl[0] = c; pl[1] = d;
}
__global__ void biassum_kernel(const float4* __restrict__ a, const float4* __restrict__ b, int n4) {
    int i = blockIdx.x * blockDim.x + threadIdx.x;
    if (i >= n4) return;
    float4 u = a[i], v = b[i];
    reinterpret_cast<float4*>(g_bsum)[i] =
        make_float4(u.x + v.x, u.y + v.y, u.z + v.z, u.w + v.w);
}

// ---- GEMM: C[M,N] = A[M,K] * W[N,K]^T, M=8192, N=K=1024 ----
#define GASTR 40
#define GEMM_SMEM (8 * 128 * GASTR * 2)

__device__ __forceinline__ void storeQKV(int z, int row, int col, float v0, float v1) {
    int b = row >> 9, n = row & 511, h = col >> 6, d = col & 63;
    size_t idx = (size_t)z * 8388608 + ((size_t)((b << 4) + h) * 512 + n) * 64 + d;
    __nv_bfloat162 hh, ll;
    split2(v0, hh.x, ll.x); split2(v1, hh.y, ll.y);
    *reinterpret_cast<__nv_bfloat162*>(g_qhi + idx) = hh;
    *reinterpret_cast<__nv_bfloat162*>(g_qlo + idx) = ll;
}

__global__ void __launch_bounds__(256, 2) gemm128(int mode, float* __restrict__ outF) {
    extern __shared__ bf16 sm[];
    const int tid = threadIdx.x, lane = tid & 31, warp = tid >> 5;
    const int wm = warp >> 2, wn = warp & 3;
    const int tm = blockIdx.y, tn = blockIdx.x, z = blockIdx.z;
    const bf16* Ahi = mode ? g_ohi : g_xhi;
    const bf16* Alo = mode ? g_olo : g_xlo;
    const int widx = mode ? 3 : z;
    const bf16* Bh = g_whi + (size_t)widx * 1048576;
    const bf16* Bl = g_wlo + (size_t)widx * 1048576;

    bf16* tiles[2][4];
    #pragma unroll
    for (int s = 0; s < 2; s++)
        #pragma unroll
        for (int t = 0; t < 4; t++) tiles[s][t] = sm + (size_t)(s * 4 + t) * (128 * GASTR);

    float acc[4][4][4] = {};
    const int c0 = tid & 3, lrow = tid >> 2;
    // ldmatrix per-lane offsets
    const int offA = (lane & 15) * GASTR + (lane >> 4) * 8;
    const int offB = ((((lane >> 4) << 3) + (lane & 7))) * GASTR + ((lane >> 3) & 1) * 8;

    auto load_stage = [&](int st, int kt) {
        const int kOff = kt * 32 + c0 * 8;
        #pragma unroll
        for (int i = 0; i < 2; i++) {
            int row = lrow + i * 64;
            int sOff = row * GASTR + c0 * 8;
            size_t gA = (size_t)(tm * 128 + row) * 1024 + kOff;
            size_t gB = (size_t)(tn * 128 + row) * 1024 + kOff;
            cp_async16(tiles[st][0] + sOff, Ahi + gA);
            cp_async16(tiles[st][1] + sOff, Alo + gA);
            cp_async16(tiles[st][2] + sOff, Bh + gB);
            cp_async16(tiles[st][3] + sOff, Bl + gB);
        }
    };

    load_stage(0, 0); cp_commit();
    int st = 0;
    for (int kt = 0; kt < 32; kt++) {
        if (kt + 1 < 32) { load_stage(st ^ 1, kt + 1); cp_commit(); cp_wait1(); }
        else             { cp_wait0(); }
        __syncthreads();
        const bf16 *sAh = tiles[st][0], *sAl = tiles[st][1];
        const bf16 *sBh = tiles[st][2], *sBl = tiles[st][3];
        #pragma unroll
        for (int kk = 0; kk < 32; kk += 16) {
            uint32_t bh[4][2], bl[4][2];
            #pragma unroll
            for (int nt2 = 0; nt2 < 2; nt2++) {
                uint32_t t[4];
                ldsm4(t, sBh + (wn * 32 + nt2 * 16) * GASTR + kk + offB);
                bh[2*nt2][0] = t[0]; bh[2*nt2][1] = t[1];
                bh[2*nt2+1][0] = t[2]; bh[2*nt2+1][1] = t[3];
                ldsm4(t, sBl + (wn * 32 + nt2 * 16) * GASTR + kk + offB);
                bl[2*nt2][0] = t[0]; bl[2*nt2][1] = t[1];
                bl[2*nt2+1][0] = t[2]; bl[2*nt2+1][1] = t[3];
            }
            #pragma unroll
            for (int mt = 0; mt < 4; mt++) {
                uint32_t ah[4], al[4];
                ldsm4(ah, sAh + (wm * 64 + mt * 16) * GASTR + kk + offA);
                ldsm4(al, sAl + (wm * 64 + mt * 16) * GASTR + kk + offA);
                #pragma unroll
                for (int nt = 0; nt < 4; nt++) {
                    mma_bf16(acc[mt][nt], ah, bh[nt]);
                    mma_bf16(acc[mt][nt], ah, bl[nt]);
                    mma_bf16(acc[mt][nt], al, bh[nt]);
                }
            }
        }
        __syncthreads();
        st ^= 1;
    }
    #pragma unroll
    for (int mt = 0; mt < 4; mt++)
        #pragma unroll
        for (int nt = 0; nt < 4; nt++) {
            int r0 = tm * 128 + wm * 64 + mt * 16 + (lane >> 2);
            int cc = tn * 128 + wn * 32 + nt * 8 + (lane & 3) * 2;
            if (mode == 0) {
                storeQKV(z, r0, cc, acc[mt][nt][0], acc[mt][nt][1]);
                storeQKV(z, r0 + 8, cc, acc[mt][nt][2], acc[mt][nt][3]);
            } else {
                *reinterpret_cast<float2*>(outF + (size_t)r0 * 1024 + cc) =
                    make_float2(acc[mt][nt][0], acc[mt][nt][1]);
                *reinterpret_cast<float2*>(outF + (size_t)(r0 + 8) * 1024 + cc) =
                    make_float2(acc[mt][nt][2], acc[mt][nt][3]);
            }
        }
}

// ---- fused attention: CTA = (b*16+h, 32 query rows) ----
#define QSTR 72
#define KSTR 72
#define SSTR 516
#define PSTR 520
#define OFF_P_HI 66048
#define OFF_P_LO 99328
#define OFF_Q_HI 132608
#define OFF_Q_LO 137216
#define OFF_KV_HI 141824
#define OFF_KV_LO 160256
#define ATTN_SMEM 178688

__global__ void __launch_bounds__(256, 1) attn_kernel() {
    extern __shared__ char smc[];
    float* Ss = reinterpret_cast<float*>(smc);
    bf16* Phi = reinterpret_cast<bf16*>(smc + OFF_P_HI);
    bf16* Plo = reinterpret_cast<bf16*>(smc + OFF_P_LO);
    bf16* Qh  = reinterpret_cast<bf16*>(smc + OFF_Q_HI);
    bf16* Ql  = reinterpret_cast<bf16*>(smc + OFF_Q_LO);
    bf16* KVh = reinterpret_cast<bf16*>(smc + OFF_KV_HI);
    bf16* KVl = reinterpret_cast<bf16*>(smc + OFF_KV_LO);

    const int tid = threadIdx.x, lane = tid & 31, warp = tid >> 5;
    const int wm = warp >> 2, wn = warp & 3;
    const int bh = blockIdx.x, rb = blockIdx.y;
    const size_t baseQ = (size_t)bh * 32768 + (size_t)rb * 2048;
    const size_t baseK = 8388608u + (size_t)bh * 32768;
    const size_t baseV = 16777216u + (size_t)bh * 32768;

    // ldmatrix per-lane offsets
    const int offAQ = (lane & 15) * QSTR + (lane >> 4) * 8;            // Q A-frag
    const int offBK = (((lane >> 4) << 3) + (lane & 7)) * KSTR + ((lane >> 3) & 1) * 8; // K B-frag
    const int offAP = (lane & 15) * PSTR + (lane >> 4) * 8;            // P A-frag
    const int offVt = ((((lane >> 3) & 1) << 3) + (lane & 7)) * KSTR + (lane >> 4) * 8; // V trans B-frag

    { // Q tile 32x64
        int row = tid >> 3, seg = (tid & 7) * 8;
        *reinterpret_cast<uint4*>(Qh + row * QSTR + seg) =
            *reinterpret_cast<const uint4*>(g_qhi + baseQ + row * 64 + seg);
        *reinterpret_cast<uint4*>(Ql + row * QSTR + seg) =
            *reinterpret_cast<const uint4*>(g_qlo + baseQ + row * 64 + seg);
    }
    const float* bs = g_bsum + ((size_t)(bh >> 4) * 512 + (size_t)rb * 32) * 512;

    // phase 1: S = scale*(Q K^T) + bias
    for (int kb = 0; kb < 4; kb++) {
        #pragma unroll
        for (int i = 0; i < 4; i++) {
            int c = tid + i * 256;
            int row = c >> 3, seg = (c & 7) * 8;
            *reinterpret_cast<uint4*>(KVh + row * KSTR + seg) =
                *reinterpret_cast<const uint4*>(g_qhi + baseK + (size_t)(kb * 128 + row) * 64 + seg);
            *reinterpret_cast<uint4*>(KVl + row * KSTR + seg) =
                *reinterpret_cast<const uint4*>(g_qlo + baseK + (size_t)(kb * 128 + row) * 64 + seg);
        }
        __syncthreads();
        float acc[4][4] = {};
        #pragma unroll
        for (int kk = 0; kk < 64; kk += 16) {
            uint32_t ah[4], al[4];
            ldsm4(ah, Qh + wm * 16 * QSTR + kk + offAQ);
            ldsm4(al, Ql + wm * 16 * QSTR + kk + offAQ);
            #pragma unroll
            for (int nt2 = 0; nt2 < 2; nt2++) {
                uint32_t tb[4], tc[4];
                ldsm4(tb, KVh + (wn * 32 + nt2 * 16) * KSTR + kk + offBK);
                ldsm4(tc, KVl + (wn * 32 + nt2 * 16) * KSTR + kk + offBK);
                uint32_t b0h[2] = { tb[0], tb[1] }, b1h[2] = { tb[2], tb[3] };
                uint32_t b0l[2] = { tc[0], tc[1] }, b1l[2] = { tc[2], tc[3] };
                mma_bf16(acc[2*nt2],   ah, b0h);
                mma_bf16(acc[2*nt2],   ah, b0l);
                mma_bf16(acc[2*nt2],   al, b0h);
                mma_bf16(acc[2*nt2+1], ah, b1h);
                mma_bf16(acc[2*nt2+1], ah, b1l);
                mma_bf16(acc[2*nt2+1], al, b1h);
            }
        }
        int qr = wm * 16 + (lane >> 2);
        #pragma unroll
        for (int nt = 0; nt < 4; nt++) {
            int key = kb * 128 + wn * 32 + nt * 8 + (lane & 3) * 2;
            float2 bv0 = *reinterpret_cast<const float2*>(bs + qr * 512 + key);
            float2 bv1 = *reinterpret_cast<const float2*>(bs + (qr + 8) * 512 + key);
            Ss[qr * SSTR + key]           = acc[nt][0] * SCALE + bv0.x;
            Ss[qr * SSTR + key + 1]       = acc[nt][1] * SCALE + bv0.y;
            Ss[(qr + 8) * SSTR + key]     = acc[nt][2] * SCALE + bv1.x;
            Ss[(qr + 8) * SSTR + key + 1] = acc[nt][3] * SCALE + bv1.y;
        }
        __syncthreads();
    }

    // phase 2: row softmax with all-zero-row masking
    #pragma unroll
    for (int rr = 0; rr < 4; rr++) {
        int r = warp * 4 + rr;
        float v[16], mx = -3.0e38f;
        bool nz = false;
        #pragma unroll
        for (int j = 0; j < 16; j++) {
            v[j] = Ss[r * SSTR + lane + j * 32];
            nz |= (v[j] != 0.0f);
            mx = fmaxf(mx, v[j]);
        }
        #pragma unroll
        for (int o = 16; o > 0; o >>= 1) mx = fmaxf(mx, __shfl_xor_sync(~0u, mx, o));
        bool rowNz = __any_sync(~0u, nz);
        float s = 0.f;
        #pragma unroll
        for (int j = 0; j < 16; j++) { v[j] = __expf(v[j] - mx); s += v[j]; }
        #pragma unroll
        for (int o = 16; o > 0; o >>= 1) s += __shfl_xor_sync(~0u, s, o);
        float inv = rowNz ? (1.0f / s) : 0.0f;
        #pragma unroll
        for (int j = 0; j < 16; j++) {
            bf16 h, l;
            split2(v[j] * inv, h, l);
            Phi[r * PSTR + lane + j * 32] = h;
            Plo[r * PSTR + lane + j * 32] = l;
        }
    }

    // phase 3: O = P V, V fragments via ldmatrix.trans (no transpose pass)
    float ao[2][4] = {};
    for (int vb = 0; vb < 4; vb++) {
        __syncthreads();
        #pragma unroll
        for (int i = 0; i < 4; i++) {
            int c = tid + i * 256;
            int row = c >> 3, seg = (c & 7) * 8;
            *reinterpret_cast<uint4*>(KVh + row * KSTR + seg) =
                *reinterpret_cast<const uint4*>(g_qhi + baseV + (size_t)(vb * 128 + row) * 64 + seg);
            *reinterpret_cast<uint4*>(KVl + row * KSTR + seg) =
                *reinterpret_cast<const uint4*>(g_qlo + baseV + (size_t)(vb * 128 + row) * 64 + seg);
        }
        __syncthreads();
        #pragma unroll
        for (int kk = 0; kk < 128; kk += 16) {
            uint32_t ah[4], al[4], tb[4], tc[4];
            ldsm4(ah, Phi + wm * 16 * PSTR + vb * 128 + kk + offAP);
            ldsm4(al, Plo + wm * 16 * PSTR + vb * 128 + kk + offAP);
            ldsm4t(tb, KVh + kk * KSTR + wn * 16 + offVt);
            ldsm4t(tc, KVl + kk * KSTR + wn * 16 + offVt);
            uint32_t b0h[2] = { tb[0], tb[1] }, b1h[2] = { tb[2], tb[3] };
            uint32_t b0l[2] = { tc[0], tc[1] }, b1l[2] = { tc[2], tc[3] };
            mma_bf16(ao[0], ah, b0h);
            mma_bf16(ao[0], ah, b0l);
            mma_bf16(ao[0], al, b0h);
            mma_bf16(ao[1], ah, b1h);
            mma_bf16(ao[1], ah, b1l);
            mma_bf16(ao[1], al, b1h);
        }
    }

    // epilogue: [b*512+q][h*64+d] hi/lo
    {
        int b = bh >> 4, h = bh & 15;
        int q0 = rb * 32 + wm * 16 + (lane >> 2);
        #pragma unroll
        for (int nt = 0; nt < 2; nt++) {
            int col = h * 64 + wn * 16 + nt * 8 + (lane & 3) * 2;
            size_t idx0 = (size_t)(b * 512 + q0) * 1024 + col;
            __nv_bfloat162 hh, ll;
            split2(ao[nt][0], hh.x, ll.x); split2(ao[nt][1], hh.y, ll.y);
            *reinterpret_cast<__nv_bfloat162*>(g_ohi + idx0) = hh;
            *reinterpret_cast<__nv_bfloat162*>(g_olo + idx0) = ll;
            split2(ao[nt][2], hh.x, ll.x); split2(ao[nt][3], hh.y, ll.y);
            *reinterpret_cast<__nv_bfloat162*>(g_ohi + idx0 + 8192) = hh;
            *reinterpret_cast<__nv_bfloat162*>(g_olo + idx0 + 8192) = ll;
        }
    }
}

extern "C" void kernel_launch(void* const* d_in, const int* in_sizes, int n_in,
                              void* d_out, int out_size) {
    const float* x  = (const float*)d_in[0];
    const float* sp = (const float*)d_in[1];
    const float* ed = (const float*)d_in[2];

    cudaFuncSetAttribute(gemm128, cudaFuncAttributeMaxDynamicSharedMemorySize, GEMM_SMEM);
    cudaFuncSetAttribute(attn_kernel, cudaFuncAttributeMaxDynamicSharedMemorySize, ATTN_SMEM);

    bf16 *xhi, *xlo;
    cudaGetSymbolAddress((void**)&xhi, g_xhi);
    cudaGetSymbolAddress((void**)&xlo, g_xlo);

    // 1: split x
    split_kernel<<<8192, 256>>>((const float4*)x, xhi, xlo, 2097152);
    // 2: split all 4 weights in one launch
    split_w_kernel<<<dim3(1024, 4), 256>>>((const float4*)d_in[3], (const float4*)d_in[4],
                                           (const float4*)d_in[5], (const float4*)d_in[6]);
    // 3: bias = spatial + edge
    biassum_kernel<<<4096, 256>>>((const float4*)sp, (const float4*)ed, 1048576);
    // 4: QKV projections
    gemm128<<<dim3(8, 64, 3), 256, GEMM_SMEM>>>(0, nullptr);
    // 5: fused attention
    attn_kernel<<<dim3(256, 16), 256, ATTN_SMEM>>>();
    // 6: output projection -> d_out (fp32)  [ncu -s 5 captures this one]
    gemm128<<<dim3(8, 64, 1), 256, GEMM_SMEM>>>(1, (float*)d_out);
}

// round 14
// speedup vs baseline: 1.8214x; 1.1962x over previous
#include <cuda_runtime.h>
#include <cuda_bf16.h>
#include <cstdint>

using bf16 = __nv_bfloat16;

#define SCALE 0.03125f  // D^-0.5, D=1024

// ---- scratch (device globals; allocation is forbidden) ----
__device__ bf16 g_xhi[8388608], g_xlo[8388608];        // x split [8192][1024]
__device__ bf16 g_whi[4194304], g_wlo[4194304];        // Wq,Wk,Wv,Wo split
__device__ bf16 g_qhi[25165824], g_qlo[25165824];      // q,k,v in [bh][n][d]
__device__ bf16 g_ohi[8388608], g_olo[8388608];        // attention out [8192][1024]
__device__ float g_bsum[4194304];                      // spatial+edge [16][512][512]

__device__ __forceinline__ void cp_async16(void* dst, const void* src) {
    uint32_t d = (uint32_t)__cvta_generic_to_shared(dst);
    asm volatile("cp.async.cg.shared.global [%0], [%1], 16;" :: "r"(d), "l"(src));
}
__device__ __forceinline__ void cp_commit() { asm volatile("cp.async.commit_group;"); }
__device__ __forceinline__ void cp_wait0()  { asm volatile("cp.async.wait_group 0;"); }
__device__ __forceinline__ void cp_wait1()  { asm volatile("cp.async.wait_group 1;"); }

__device__ __forceinline__ void ldsm4(uint32_t r[4], const bf16* p) {
    uint32_t a = (uint32_t)__cvta_generic_to_shared(p);
    asm volatile("ldmatrix.sync.aligned.m8n8.x4.shared.b16 {%0,%1,%2,%3}, [%4];"
                 : "=r"(r[0]), "=r"(r[1]), "=r"(r[2]), "=r"(r[3]) : "r"(a));
}
__device__ __forceinline__ void ldsm4t(uint32_t r[4], const bf16* p) {
    uint32_t a = (uint32_t)__cvta_generic_to_shared(p);
    asm volatile("ldmatrix.sync.aligned.m8n8.x4.trans.shared.b16 {%0,%1,%2,%3}, [%4];"
                 : "=r"(r[0]), "=r"(r[1]), "=r"(r[2]), "=r"(r[3]) : "r"(a));
}
__device__ __forceinline__ void mma_bf16(float c[4], const uint32_t a[4], const uint32_t b[2]) {
    asm volatile(
        "mma.sync.aligned.m16n8k16.row.col.f32.bf16.bf16.f32 "
        "{%0,%1,%2,%3}, {%4,%5,%6,%7}, {%8,%9}, {%0,%1,%2,%3};"
        : "+f"(c[0]), "+f"(c[1]), "+f"(c[2]), "+f"(c[3])
        : "r"(a[0]), "r"(a[1]), "r"(a[2]), "r"(a[3]), "r"(b[0]), "r"(b[1]));
}
__device__ __forceinline__ void split2(float v, bf16& h, bf16& l) {
    h = __float2bfloat16(v);
    l = __float2bfloat16(v - __bfloat162float(h));
}
__device__ __forceinline__ uint32_t packhl(bf16 a, bf16 b) {
    __nv_bfloat162 t; t.x = a; t.y = b;
    return *reinterpret_cast<uint32_t*>(&t);
}

// ---- prep ----
__global__ void split_kernel(const float4* __restrict__ src, bf16* hi, bf16* lo, int n4) {
    int i = blockIdx.x * blockDim.x + threadIdx.x;
    if (i >= n4) return;
    float4 v = src[i];
    __nv_bfloat162 a, b, c, d;
    split2(v.x, a.x, c.x); split2(v.y, a.y, c.y);
    split2(v.z, b.x, d.x); split2(v.w, b.y, d.y);
    __nv_bfloat162* ph = reinterpret_cast<__nv_bfloat162*>(hi) + 2 * i;
    ph[0] = a; ph[1] = b;
    __nv_bfloat162* pl = reinterpret_cast<__nv_bfloat162*>(lo) + 2 * i;
    pl[0] = c; pl[1] = d;
}
__global__ void split_w_kernel(const float4* __restrict__ w0, const float4* __restrict__ w1,
                               const float4* __restrict__ w2, const float4* __restrict__ w3) {
    int y = blockIdx.y;
    const float4* src = (y == 0) ? w0 : (y == 1) ? w1 : (y == 2) ? w2 : w3;
    int i = blockIdx.x * blockDim.x + threadIdx.x;
    float4 v = src[i];
    __nv_bfloat162 a, b, c, d;
    split2(v.x, a.x, c.x); split2(v.y, a.y, c.y);
    split2(v.z, b.x, d.x); split2(v.w, b.y, d.y);
    size_t base = (size_t)y * 524288 + 2 * (size_t)i;
    __nv_bfloat162* ph = reinterpret_cast<__nv_bfloat162*>(g_whi) + base;
    ph[0] = a; ph[1] = b;
    __nv_bfloat162* pl = reinterpret_cast<__nv_bfloat162*>(g_wlo) + base;
    pl[0] = c; pl[1] = d;
}
__global__ void biassum_kernel(const float4* __restrict__ a, const float4* __restrict__ b, int n4) {
    int i = blockIdx.x * blockDim.x + threadIdx.x;
    if (i >= n4) return;
    float4 u = a[i], v = b[i];
    reinterpret_cast<float4*>(g_bsum)[i] =
        make_float4(u.x + v.x, u.y + v.y, u.z + v.z, u.w + v.w);
}

// ---- GEMM (round-12, passing): C[M,N] = A[M,K] * W[N,K]^T ----
#define GASTR 40
#define GEMM_SMEM (8 * 128 * GASTR * 2)

__device__ __forceinline__ void storeQKV(int z, int row, int col, float v0, float v1) {
    int b = row >> 9, n = row & 511, h = col >> 6, d = col & 63;
    size_t idx = (size_t)z * 8388608 + ((size_t)((b << 4) + h) * 512 + n) * 64 + d;
    __nv_bfloat162 hh, ll;
    split2(v0, hh.x, ll.x); split2(v1, hh.y, ll.y);
    *reinterpret_cast<__nv_bfloat162*>(g_qhi + idx) = hh;
    *reinterpret_cast<__nv_bfloat162*>(g_qlo + idx) = ll;
}

__global__ void __launch_bounds__(256, 2) gemm128(int mode, float* __restrict__ outF) {
    extern __shared__ bf16 sm[];
    const int tid = threadIdx.x, lane = tid & 31, warp = tid >> 5;
    const int wm = warp >> 2, wn = warp & 3;
    const int tm = blockIdx.y, tn = blockIdx.x, z = blockIdx.z;
    const bf16* Ahi = mode ? g_ohi : g_xhi;
    const bf16* Alo = mode ? g_olo : g_xlo;
    const int widx = mode ? 3 : z;
    const bf16* Bh = g_whi + (size_t)widx * 1048576;
    const bf16* Bl = g_wlo + (size_t)widx * 1048576;

    bf16* tiles[2][4];
    #pragma unroll
    for (int s = 0; s < 2; s++)
        #pragma unroll
        for (int t = 0; t < 4; t++) tiles[s][t] = sm + (size_t)(s * 4 + t) * (128 * GASTR);

    float acc[4][4][4] = {};
    const int c0 = tid & 3, lrow = tid >> 2;
    const int offA = (lane & 15) * GASTR + (lane >> 4) * 8;
    const int offB = ((((lane >> 4) << 3) + (lane & 7))) * GASTR + ((lane >> 3) & 1) * 8;

    auto load_stage = [&](int st, int kt) {
        const int kOff = kt * 32 + c0 * 8;
        #pragma unroll
        for (int i = 0; i < 2; i++) {
            int row = lrow + i * 64;
            int sOff = row * GASTR + c0 * 8;
            size_t gA = (size_t)(tm * 128 + row) * 1024 + kOff;
            size_t gB = (size_t)(tn * 128 + row) * 1024 + kOff;
            cp_async16(tiles[st][0] + sOff, Ahi + gA);
            cp_async16(tiles[st][1] + sOff, Alo + gA);
            cp_async16(tiles[st][2] + sOff, Bh + gB);
            cp_async16(tiles[st][3] + sOff, Bl + gB);
        }
    };

    load_stage(0, 0); cp_commit();
    int st = 0;
    for (int kt = 0; kt < 32; kt++) {
        if (kt + 1 < 32) { load_stage(st ^ 1, kt + 1); cp_commit(); cp_wait1(); }
        else             { cp_wait0(); }
        __syncthreads();
        const bf16 *sAh = tiles[st][0], *sAl = tiles[st][1];
        const bf16 *sBh = tiles[st][2], *sBl = tiles[st][3];
        #pragma unroll
        for (int kk = 0; kk < 32; kk += 16) {
            uint32_t bh[4][2], bl[4][2];
            #pragma unroll
            for (int nt2 = 0; nt2 < 2; nt2++) {
                uint32_t t[4];
                ldsm4(t, sBh + (wn * 32 + nt2 * 16) * GASTR + kk + offB);
                bh[2*nt2][0] = t[0]; bh[2*nt2][1] = t[1];
                bh[2*nt2+1][0] = t[2]; bh[2*nt2+1][1] = t[3];
                ldsm4(t, sBl + (wn * 32 + nt2 * 16) * GASTR + kk + offB);
                bl[2*nt2][0] = t[0]; bl[2*nt2][1] = t[1];
                bl[2*nt2+1][0] = t[2]; bl[2*nt2+1][1] = t[3];
            }
            #pragma unroll
            for (int mt = 0; mt < 4; mt++) {
                uint32_t ah[4], al[4];
                ldsm4(ah, sAh + (wm * 64 + mt * 16) * GASTR + kk + offA);
                ldsm4(al, sAl + (wm * 64 + mt * 16) * GASTR + kk + offA);
                #pragma unroll
                for (int nt = 0; nt < 4; nt++) {
                    mma_bf16(acc[mt][nt], ah, bh[nt]);
                    mma_bf16(acc[mt][nt], ah, bl[nt]);
                    mma_bf16(acc[mt][nt], al, bh[nt]);
                }
            }
        }
        __syncthreads();
        st ^= 1;
    }
    #pragma unroll
    for (int mt = 0; mt < 4; mt++)
        #pragma unroll
        for (int nt = 0; nt < 4; nt++) {
            int r0 = tm * 128 + wm * 64 + mt * 16 + (lane >> 2);
            int cc = tn * 128 + wn * 32 + nt * 8 + (lane & 3) * 2;
            if (mode == 0) {
                storeQKV(z, r0, cc, acc[mt][nt][0], acc[mt][nt][1]);
                storeQKV(z, r0 + 8, cc, acc[mt][nt][2], acc[mt][nt][3]);
            } else {
                *reinterpret_cast<float2*>(outF + (size_t)r0 * 1024 + cc) =
                    make_float2(acc[mt][nt][0], acc[mt][nt][1]);
                *reinterpret_cast<float2*>(outF + (size_t)(r0 + 8) * 1024 + cc) =
                    make_float2(acc[mt][nt][2], acc[mt][nt][3]);
            }
        }
}

// ---- fused attention, register-resident P (flash-style, key-split) ----
// CTA = (bh, 32 query rows). 8 warps: wm=warp>>2 picks 16-row half, wn=warp&3 owns
// 32 keys per 128-key block (128 keys total per warp across 4 blocks).
// No max-subtraction: logits bounded (~|a|<15), exp() safe in fp32; normalize at end.
#define QSTR 72
#define KSTR 72
#define A_OFF_QH 0
#define A_OFF_QL 4608
#define A_OFF_KH 9216
#define A_OFF_KL 27648
#define A_OFF_VH 46080
#define A_OFF_VL 64512
#define A_OFF_SRED 82944
#define A_OFF_NZ  83456
#define A_OFF_OP  9216      /* reuses K region after last QK */
#define ATTN_SMEM 83968

__global__ void __launch_bounds__(256, 2) attn_kernel() {
    extern __shared__ char smc[];
    bf16* Qh = reinterpret_cast<bf16*>(smc + A_OFF_QH);
    bf16* Ql = reinterpret_cast<bf16*>(smc + A_OFF_QL);
    bf16* Kh = reinterpret_cast<bf16*>(smc + A_OFF_KH);
    bf16* Kl = reinterpret_cast<bf16*>(smc + A_OFF_KL);
    bf16* Vh = reinterpret_cast<bf16*>(smc + A_OFF_VH);
    bf16* Vl = reinterpret_cast<bf16*>(smc + A_OFF_VL);
    float* sred  = reinterpret_cast<float*>(smc + A_OFF_SRED);  // [8 warps][16 rows]
    float* nzred = reinterpret_cast<float*>(smc + A_OFF_NZ);
    float* opart = reinterpret_cast<float*>(smc + A_OFF_OP);    // [4 wn][32][64]

    const int tid = threadIdx.x, lane = tid & 31, warp = tid >> 5;
    const int wm = warp >> 2, wn = warp & 3;
    const int bh = blockIdx.x, rb = blockIdx.y;
    const size_t baseQ = (size_t)bh * 32768 + (size_t)rb * 2048;
    const size_t baseK = 8388608u + (size_t)bh * 32768;
    const size_t baseV = 16777216u + (size_t)bh * 32768;

    const int offAQ = (lane & 15) * QSTR + (lane >> 4) * 8;
    const int offBK = (((lane >> 4) << 3) + (lane & 7)) * KSTR + ((lane >> 3) & 1) * 8;
    const int offVt = ((((lane >> 3) & 1) << 3) + (lane & 7)) * KSTR + (lane >> 4) * 8;
    const int r0l = lane >> 2, c2 = (lane & 3) * 2;

    { // Q tile 32x64 hi/lo
        int row = tid >> 3, seg = (tid & 7) * 8;
        *reinterpret_cast<uint4*>(Qh + row * QSTR + seg) =
            *reinterpret_cast<const uint4*>(g_qhi + baseQ + row * 64 + seg);
        *reinterpret_cast<uint4*>(Ql + row * QSTR + seg) =
            *reinterpret_cast<const uint4*>(g_qlo + baseQ + row * 64 + seg);
    }
    const float* bs = g_bsum + ((size_t)(bh >> 4) * 512 + (size_t)rb * 32) * 512;

    float ao[8][4] = {};
    float s0 = 0.f, s1 = 0.f, nz0 = 0.f, nz1 = 0.f;

    for (int kb = 0; kb < 4; kb++) {
        if (kb) __syncthreads();   // previous block's K/V reads complete
        #pragma unroll
        for (int i = 0; i < 4; i++) {
            int c = tid + i * 256;
            int row = c >> 3, seg = (c & 7) * 8;
            size_t gk = baseK + (size_t)(kb * 128 + row) * 64 + seg;
            size_t gv = baseV + (size_t)(kb * 128 + row) * 64 + seg;
            cp_async16(Kh + row * KSTR + seg, g_qhi + gk);
            cp_async16(Kl + row * KSTR + seg, g_qlo + gk);
            cp_async16(Vh + row * KSTR + seg, g_qhi + gv);
            cp_async16(Vl + row * KSTR + seg, g_qlo + gv);
        }
        cp_commit(); cp_wait0();
        __syncthreads();

        // QK^T for this warp's 32 keys
        float L[4][4] = {};
        #pragma unroll
        for (int kk = 0; kk < 64; kk += 16) {
            uint32_t ah[4], al[4];
            ldsm4(ah, Qh + wm * 16 * QSTR + kk + offAQ);
            ldsm4(al, Ql + wm * 16 * QSTR + kk + offAQ);
            #pragma unroll
            for (int nt2 = 0; nt2 < 2; nt2++) {
                uint32_t tb[4], tc[4];
                ldsm4(tb, Kh + (wn * 32 + nt2 * 16) * KSTR + kk + offBK);
                ldsm4(tc, Kl + (wn * 32 + nt2 * 16) * KSTR + kk + offBK);
                uint32_t b0h[2] = { tb[0], tb[1] }, b1h[2] = { tb[2], tb[3] };
                uint32_t b0l[2] = { tc[0], tc[1] }, b1l[2] = { tc[2], tc[3] };
                mma_bf16(L[2*nt2],   ah, b0h);
                mma_bf16(L[2*nt2],   ah, b0l);
                mma_bf16(L[2*nt2],   al, b0h);
                mma_bf16(L[2*nt2+1], ah, b1h);
                mma_bf16(L[2*nt2+1], ah, b1l);
                mma_bf16(L[2*nt2+1], al, b1h);
            }
        }

        // logits -> unnormalized p (bf16 hi/lo) in registers
        uint32_t pH0[4], pH1[4], pL0[4], pL1[4];
        const float* bsr = bs + (size_t)(wm * 16 + r0l) * 512 + kb * 128 + wn * 32 + c2;
        #pragma unroll
        for (int nt = 0; nt < 4; nt++) {
            float2 b0 = *reinterpret_cast<const float2*>(bsr + nt * 8);
            float2 b1 = *reinterpret_cast<const float2*>(bsr + nt * 8 + 8 * 512);
            float a0 = fmaf(L[nt][0], SCALE, b0.x);
            float a1 = fmaf(L[nt][1], SCALE, b0.y);
            float a2 = fmaf(L[nt][2], SCALE, b1.x);
            float a3 = fmaf(L[nt][3], SCALE, b1.y);
            if (a0 != 0.f || a1 != 0.f) nz0 = 1.f;
            if (a2 != 0.f || a3 != 0.f) nz1 = 1.f;
            float e0 = __expf(a0), e1 = __expf(a1), e2 = __expf(a2), e3 = __expf(a3);
            s0 += e0 + e1; s1 += e2 + e3;
            bf16 h0, l0, h1, l1;
            split2(e0, h0, l0); split2(e1, h1, l1);
            pH0[nt] = packhl(h0, h1); pL0[nt] = packhl(l0, l1);
            split2(e2, h0, l0); split2(e3, h1, l1);
            pH1[nt] = packhl(h0, h1); pL1[nt] = packhl(l0, l1);
        }

        // P·V for this warp's 32 keys, all 64 output dims
        #pragma unroll
        for (int kc = 0; kc < 2; kc++) {
            const int nt0 = kc * 2;
            uint32_t aH[4] = { pH0[nt0], pH1[nt0], pH0[nt0+1], pH1[nt0+1] };
            uint32_t aL[4] = { pL0[nt0], pL1[nt0], pL0[nt0+1], pL1[nt0+1] };
            const bf16* vb = Vh + (wn * 32 + kc * 16) * KSTR;
            const bf16* vc = Vl + (wn * 32 + kc * 16) * KSTR;
            #pragma unroll
            for (int dc = 0; dc < 4; dc++) {
                uint32_t tb[4], tc[4];
                ldsm4t(tb, vb + dc * 16 + offVt);
                ldsm4t(tc, vc + dc * 16 + offVt);
                uint32_t b0h[2] = { tb[0], tb[1] }, b1h[2] = { tb[2], tb[3] };
                uint32_t b0l[2] = { tc[0], tc[1] }, b1l[2] = { tc[2], tc[3] };
                mma_bf16(ao[dc*2],   aH, b0h);
                mma_bf16(ao[dc*2],   aH, b0l);
                mma_bf16(ao[dc*2],   aL, b0h);
                mma_bf16(ao[dc*2+1], aH, b1h);
                mma_bf16(ao[dc*2+1], aH, b1l);
                mma_bf16(ao[dc*2+1], aL, b1h);
            }
        }
    }

    // quad-reduce row sums / nz (lanes in a quad share the same rows)
    s0 += __shfl_xor_sync(~0u, s0, 1); s0 += __shfl_xor_sync(~0u, s0, 2);
    s1 += __shfl_xor_sync(~0u, s1, 1); s1 += __shfl_xor_sync(~0u, s1, 2);
    nz0 += __shfl_xor_sync(~0u, nz0, 1); nz0 += __shfl_xor_sync(~0u, nz0, 2);
    nz1 += __shfl_xor_sync(~0u, nz1, 1); nz1 += __shfl_xor_sync(~0u, nz1, 2);

    __syncthreads();   // all QK/PV reads of K region done before opart overwrites it
    if ((lane & 3) == 0) {
        sred[warp * 16 + r0l] = s0;  sred[warp * 16 + r0l + 8] = s1;
        nzred[warp * 16 + r0l] = nz0; nzred[warp * 16 + r0l + 8] = nz1;
    }
    {   // store per-warp O partials: opart[wn][row 0..31][d 0..63]
        float* op = opart + wn * 2048;
        int rr0 = wm * 16 + r0l;
        #pragma unroll
        for (int dc = 0; dc < 4; dc++)
            #pragma unroll
            for (int j = 0; j < 2; j++) {
                int col = dc * 16 + j * 8 + c2;
                *reinterpret_cast<float2*>(op + rr0 * 64 + col) =
                    make_float2(ao[dc*2+j][0], ao[dc*2+j][1]);
                *reinterpret_cast<float2*>(op + (rr0 + 8) * 64 + col) =
                    make_float2(ao[dc*2+j][2], ao[dc*2+j][3]);
            }
    }
    __syncthreads();

    // final: merge 4 key-partials, normalize, write hi/lo
    {
        int row = tid >> 3, d0 = (tid & 7) * 8;
        int row16 = row & 15, wmr = row >> 4;
        float s = sred[(wmr*4+0)*16 + row16] + sred[(wmr*4+1)*16 + row16]
                + sred[(wmr*4+2)*16 + row16] + sred[(wmr*4+3)*16 + row16];
        float nzt = nzred[(wmr*4+0)*16 + row16] + nzred[(wmr*4+1)*16 + row16]
                  + nzred[(wmr*4+2)*16 + row16] + nzred[(wmr*4+3)*16 + row16];
        float inv = (nzt > 0.f) ? (1.f / s) : 0.f;
        __align__(16) bf16 hs[8], ls[8];
        #pragma unroll
        for (int j = 0; j < 8; j++) {
            float o = (opart[row * 64 + d0 + j] + opart[2048 + row * 64 + d0 + j]
                     + opart[4096 + row * 64 + d0 + j] + opart[6144 + row * 64 + d0 + j]) * inv;
            split2(o, hs[j], ls[j]);
        }
        int b = bh >> 4, h = bh & 15;
        size_t gidx = ((size_t)(b * 512 + rb * 32 + row)) * 1024 + h * 64 + d0;
        *reinterpret_cast<uint4*>(g_ohi + gidx) = *reinterpret_cast<uint4*>(hs);
        *reinterpret_cast<uint4*>(g_olo + gidx) = *reinterpret_cast<uint4*>(ls);
    }
}

extern "C" void kernel_launch(void* const* d_in, const int* in_sizes, int n_in,
                              void* d_out, int out_size) {
    const float* x  = (const float*)d_in[0];
    const float* sp = (const float*)d_in[1];
    const float* ed = (const float*)d_in[2];

    cudaFuncSetAttribute(gemm128, cudaFuncAttributeMaxDynamicSharedMemorySize, GEMM_SMEM);
    cudaFuncSetAttribute(attn_kernel, cudaFuncAttributeMaxDynamicSharedMemorySize, ATTN_SMEM);

    bf16 *xhi, *xlo;
    cudaGetSymbolAddress((void**)&xhi, g_xhi);
    cudaGetSymbolAddress((void**)&xlo, g_xlo);

    split_kernel<<<8192, 256>>>((const float4*)x, xhi, xlo, 2097152);
    split_w_kernel<<<dim3(1024, 4), 256>>>((const float4*)d_in[3], (const float4*)d_in[4],
                                           (const float4*)d_in[5], (const float4*)d_in[6]);
    biassum_kernel<<<4096, 256>>>((const float4*)sp, (const float4*)ed, 1048576);
    // QKV projections
    gemm128<<<dim3(8, 64, 3), 256, GEMM_SMEM>>>(0, nullptr);
    // fused attention (register-resident P)
    attn_kernel<<<dim3(256, 16), 256, ATTN_SMEM>>>();
    // output projection -> d_out (fp32)
    gemm128<<<dim3(8, 64, 1), 256, GEMM_SMEM>>>(1, (float*)d_out);
}

// round 15
// speedup vs baseline: 2.0335x; 1.1165x over previous
#include <cuda_runtime.h>
#include <cuda_bf16.h>
#include <cstdint>

using bf16 = __nv_bfloat16;

#define SCALE 0.03125f  // D^-0.5, D=1024

// ---- scratch (device globals; allocation is forbidden) ----
__device__ bf16 g_xhi[8388608], g_xlo[8388608];        // x split [8192][1024]
__device__ bf16 g_whi[4194304], g_wlo[4194304];        // Wq,Wk,Wv,Wo split
__device__ bf16 g_qhi[25165824], g_qlo[25165824];      // q,k,v in [bh][n][d]
__device__ bf16 g_ohi[8388608], g_olo[8388608];        // attention out [8192][1024]
__device__ float g_bsum[4194304];                      // spatial+edge [16][512][512]

__device__ __forceinline__ void cp_async16(void* dst, const void* src) {
    uint32_t d = (uint32_t)__cvta_generic_to_shared(dst);
    asm volatile("cp.async.cg.shared.global [%0], [%1], 16;" :: "r"(d), "l"(src));
}
__device__ __forceinline__ void cp_commit() { asm volatile("cp.async.commit_group;"); }
__device__ __forceinline__ void cp_wait0()  { asm volatile("cp.async.wait_group 0;"); }
__device__ __forceinline__ void cp_wait1()  { asm volatile("cp.async.wait_group 1;"); }

__device__ __forceinline__ void ldsm4(uint32_t r[4], const void* p) {
    uint32_t a = (uint32_t)__cvta_generic_to_shared(p);
    asm volatile("ldmatrix.sync.aligned.m8n8.x4.shared.b16 {%0,%1,%2,%3}, [%4];"
                 : "=r"(r[0]), "=r"(r[1]), "=r"(r[2]), "=r"(r[3]) : "r"(a));
}
__device__ __forceinline__ void ldsm4t(uint32_t r[4], const void* p) {
    uint32_t a = (uint32_t)__cvta_generic_to_shared(p);
    asm volatile("ldmatrix.sync.aligned.m8n8.x4.trans.shared.b16 {%0,%1,%2,%3}, [%4];"
                 : "=r"(r[0]), "=r"(r[1]), "=r"(r[2]), "=r"(r[3]) : "r"(a));
}
__device__ __forceinline__ void mma_bf16(float c[4], const uint32_t a[4], const uint32_t b[2]) {
    asm volatile(
        "mma.sync.aligned.m16n8k16.row.col.f32.bf16.bf16.f32 "
        "{%0,%1,%2,%3}, {%4,%5,%6,%7}, {%8,%9}, {%0,%1,%2,%3};"
        : "+f"(c[0]), "+f"(c[1]), "+f"(c[2]), "+f"(c[3])
        : "r"(a[0]), "r"(a[1]), "r"(a[2]), "r"(a[3]), "r"(b[0]), "r"(b[1]));
}
__device__ __forceinline__ void split2(float v, bf16& h, bf16& l) {
    h = __float2bfloat16(v);
    l = __float2bfloat16(v - __bfloat162float(h));
}
__device__ __forceinline__ uint32_t packhl(bf16 a, bf16 b) {
    __nv_bfloat162 t; t.x = a; t.y = b;
    return *reinterpret_cast<uint32_t*>(&t);
}

// ---- prep ----
__global__ void split_kernel(const float4* __restrict__ src, bf16* hi, bf16* lo, int n4) {
    int i = blockIdx.x * blockDim.x + threadIdx.x;
    if (i >= n4) return;
    float4 v = src[i];
    __nv_bfloat162 a, b, c, d;
    split2(v.x, a.x, c.x); split2(v.y, a.y, c.y);
    split2(v.z, b.x, d.x); split2(v.w, b.y, d.y);
    __nv_bfloat162* ph = reinterpret_cast<__nv_bfloat162*>(hi) + 2 * i;
    ph[0] = a; ph[1] = b;
    __nv_bfloat162* pl = reinterpret_cast<__nv_bfloat162*>(lo) + 2 * i;
    pl[0] = c; pl[1] = d;
}
__global__ void split_w_kernel(const float4* __restrict__ w0, const float4* __restrict__ w1,
                               const float4* __restrict__ w2, const float4* __restrict__ w3) {
    int y = blockIdx.y;
    const float4* src = (y == 0) ? w0 : (y == 1) ? w1 : (y == 2) ? w2 : w3;
    int i = blockIdx.x * blockDim.x + threadIdx.x;
    float4 v = src[i];
    __nv_bfloat162 a, b, c, d;
    split2(v.x, a.x, c.x); split2(v.y, a.y, c.y);
    split2(v.z, b.x, d.x); split2(v.w, b.y, d.y);
    size_t base = (size_t)y * 524288 + 2 * (size_t)i;
    __nv_bfloat162* ph = reinterpret_cast<__nv_bfloat162*>(g_whi) + base;
    ph[0] = a; ph[1] = b;
    __nv_bfloat162* pl = reinterpret_cast<__nv_bfloat162*>(g_wlo) + base;
    pl[0] = c; pl[1] = d;
}
__global__ void biassum_kernel(const float4* __restrict__ a, const float4* __restrict__ b, int n4) {
    int i = blockIdx.x * blockDim.x + threadIdx.x;
    if (i >= n4) return;
    float4 u = a[i], v = b[i];
    reinterpret_cast<float4*>(g_bsum)[i] =
        make_float4(u.x + v.x, u.y + v.y, u.z + v.z, u.w + v.w);
}

// ---- GEMM: C[M,N] = A[M,K] * W[N,K]^T, 128x128 CTA tile, 3-stage pipeline ----
// smem row = 128 B = [hi k0..31 | lo k0..31], XOR swizzle seg^(row&7).
#define STG 32768
#define GEMM_SMEM (3 * STG)   // 98304

__device__ __forceinline__ void storeQKV(int z, int row, int col, float v0, float v1) {
    int b = row >> 9, n = row & 511, h = col >> 6, d = col & 63;
    size_t idx = (size_t)z * 8388608 + ((size_t)((b << 4) + h) * 512 + n) * 64 + d;
    __nv_bfloat162 hh, ll;
    split2(v0, hh.x, ll.x); split2(v1, hh.y, ll.y);
    *reinterpret_cast<__nv_bfloat162*>(g_qhi + idx) = hh;
    *reinterpret_cast<__nv_bfloat162*>(g_qlo + idx) = ll;
}

__global__ void __launch_bounds__(256, 2) gemm128(int mode, float* __restrict__ outF) {
    extern __shared__ char smc[];
    const int tid = threadIdx.x, lane = tid & 31, warp = tid >> 5;
    const int wm = warp >> 2, wn = warp & 3;
    const int tm = blockIdx.y, tn = blockIdx.x, z = blockIdx.z;
    const bf16* Ahi = mode ? g_ohi : g_xhi;
    const bf16* Alo = mode ? g_olo : g_xlo;
    const int widx = mode ? 3 : z;
    const bf16* Bh = g_whi + (size_t)widx * 1048576;
    const bf16* Bl = g_wlo + (size_t)widx * 1048576;

    float acc[4][4][4] = {};

    // ldmatrix byte offsets within a tile (per-lane, per kk-half, hi/lo)
    const int rA = lane & 15, sA = lane >> 4, xA = rA & 7;
    const int rB = ((lane >> 4) << 3) + (lane & 7), sB = (lane >> 3) & 1, xB = rB & 7;
    int offAh[2], offAl[2], offBh[2], offBl[2];
    #pragma unroll
    for (int c = 0; c < 2; c++) {
        offAh[c] = rA * 128 + (((c * 2 + sA)     ^ xA) << 4);
        offAl[c] = rA * 128 + (((c * 2 + sA + 4) ^ xA) << 4);
        offBh[c] = rB * 128 + (((c * 2 + sB)     ^ xB) << 4);
        offBl[c] = rB * 128 + (((c * 2 + sB + 4) ^ xB) << 4);
    }

    auto load_stage = [&](int st, int kt) {
        char* base = smc + st * STG;
        const int kOff = kt * 32;
        #pragma unroll
        for (int i = 0; i < 4; i++) {      // A: 128 rows x 8 segs
            int s = tid + i * 256;
            int r = s >> 3, c8 = s & 7;
            const bf16* src = (c8 < 4 ? Ahi : Alo) +
                              (size_t)(tm * 128 + r) * 1024 + kOff + (c8 & 3) * 8;
            cp_async16(base + r * 128 + ((c8 ^ (r & 7)) << 4), src);
        }
        #pragma unroll
        for (int i = 0; i < 4; i++) {      // B
            int s = tid + i * 256;
            int r = s >> 3, c8 = s & 7;
            const bf16* src = (c8 < 4 ? Bh : Bl) +
                              (size_t)(tn * 128 + r) * 1024 + kOff + (c8 & 3) * 8;
            cp_async16(base + 16384 + r * 128 + ((c8 ^ (r & 7)) << 4), src);
        }
        cp_commit();
    };

    load_stage(0, 0);
    load_stage(1, 1);
    int st = 0;
    for (int kt = 0; kt < 32; kt++) {
        if (kt + 1 < 32) cp_wait1(); else cp_wait0();
        __syncthreads();
        if (kt + 2 < 32) {
            int stL = st + 2; if (stL >= 3) stL -= 3;
            load_stage(stL, kt + 2);
        }
        const char* At = smc + st * STG;
        const char* Bt = At + 16384;
        #pragma unroll
        for (int c = 0; c < 2; c++) {      // kk = c*16
            uint32_t bh[4][2], bl[4][2];
            #pragma unroll
            for (int nt2 = 0; nt2 < 2; nt2++) {
                uint32_t t[4];
                ldsm4(t, Bt + (wn * 32 + nt2 * 16) * 128 + offBh[c]);
                bh[2*nt2][0] = t[0]; bh[2*nt2][1] = t[1];
                bh[2*nt2+1][0] = t[2]; bh[2*nt2+1][1] = t[3];
                ldsm4(t, Bt + (wn * 32 + nt2 * 16) * 128 + offBl[c]);
                bl[2*nt2][0] = t[0]; bl[2*nt2][1] = t[1];
                bl[2*nt2+1][0] = t[2]; bl[2*nt2+1][1] = t[3];
            }
            #pragma unroll
            for (int mt = 0; mt < 4; mt++) {
                uint32_t ah[4], al[4];
                ldsm4(ah, At + (wm * 64 + mt * 16) * 128 + offAh[c]);
                ldsm4(al, At + (wm * 64 + mt * 16) * 128 + offAl[c]);
                #pragma unroll
                for (int nt = 0; nt < 4; nt++) {
                    mma_bf16(acc[mt][nt], ah, bh[nt]);
                    mma_bf16(acc[mt][nt], ah, bl[nt]);
                    mma_bf16(acc[mt][nt], al, bh[nt]);
                }
            }
        }
        if (++st == 3) st = 0;
    }
    #pragma unroll
    for (int mt = 0; mt < 4; mt++)
        #pragma unroll
        for (int nt = 0; nt < 4; nt++) {
            int r0 = tm * 128 + wm * 64 + mt * 16 + (lane >> 2);
            int cc = tn * 128 + wn * 32 + nt * 8 + (lane & 3) * 2;
            if (mode == 0) {
                storeQKV(z, r0, cc, acc[mt][nt][0], acc[mt][nt][1]);
                storeQKV(z, r0 + 8, cc, acc[mt][nt][2], acc[mt][nt][3]);
            } else {
                *reinterpret_cast<float2*>(outF + (size_t)r0 * 1024 + cc) =
                    make_float2(acc[mt][nt][0], acc[mt][nt][1]);
                *reinterpret_cast<float2*>(outF + (size_t)(r0 + 8) * 1024 + cc) =
                    make_float2(acc[mt][nt][2], acc[mt][nt][3]);
            }
        }
}

// ---- fused attention, register-resident P (round-14, passing) ----
#define QSTR 72
#define KSTR 72
#define A_OFF_QH 0
#define A_OFF_QL 4608
#define A_OFF_KH 9216
#define A_OFF_KL 27648
#define A_OFF_VH 46080
#define A_OFF_VL 64512
#define A_OFF_SRED 82944
#define A_OFF_NZ  83456
#define A_OFF_OP  9216      /* reuses K region after last QK */
#define ATTN_SMEM 83968

__global__ void __launch_bounds__(256, 2) attn_kernel() {
    extern __shared__ char smc[];
    bf16* Qh = reinterpret_cast<bf16*>(smc + A_OFF_QH);
    bf16* Ql = reinterpret_cast<bf16*>(smc + A_OFF_QL);
    bf16* Kh = reinterpret_cast<bf16*>(smc + A_OFF_KH);
    bf16* Kl = reinterpret_cast<bf16*>(smc + A_OFF_KL);
    bf16* Vh = reinterpret_cast<bf16*>(smc + A_OFF_VH);
    bf16* Vl = reinterpret_cast<bf16*>(smc + A_OFF_VL);
    float* sred  = reinterpret_cast<float*>(smc + A_OFF_SRED);
    float* nzred = reinterpret_cast<float*>(smc + A_OFF_NZ);
    float* opart = reinterpret_cast<float*>(smc + A_OFF_OP);

    const int tid = threadIdx.x, lane = tid & 31, warp = tid >> 5;
    const int wm = warp >> 2, wn = warp & 3;
    const int bh = blockIdx.x, rb = blockIdx.y;
    const size_t baseQ = (size_t)bh * 32768 + (size_t)rb * 2048;
    const size_t baseK = 8388608u + (size_t)bh * 32768;
    const size_t baseV = 16777216u + (size_t)bh * 32768;

    const int offAQ = (lane & 15) * QSTR + (lane >> 4) * 8;
    const int offBK = (((lane >> 4) << 3) + (lane & 7)) * KSTR + ((lane >> 3) & 1) * 8;
    const int offVt = ((((lane >> 3) & 1) << 3) + (lane & 7)) * KSTR + (lane >> 4) * 8;
    const int r0l = lane >> 2, c2 = (lane & 3) * 2;

    {
        int row = tid >> 3, seg = (tid & 7) * 8;
        *reinterpret_cast<uint4*>(Qh + row * QSTR + seg) =
            *reinterpret_cast<const uint4*>(g_qhi + baseQ + row * 64 + seg);
        *reinterpret_cast<uint4*>(Ql + row * QSTR + seg) =
            *reinterpret_cast<const uint4*>(g_qlo + baseQ + row * 64 + seg);
    }
    const float* bs = g_bsum + ((size_t)(bh >> 4) * 512 + (size_t)rb * 32) * 512;

    float ao[8][4] = {};
    float s0 = 0.f, s1 = 0.f, nz0 = 0.f, nz1 = 0.f;

    for (int kb = 0; kb < 4; kb++) {
        if (kb) __syncthreads();
        #pragma unroll
        for (int i = 0; i < 4; i++) {
            int c = tid + i * 256;
            int row = c >> 3, seg = (c & 7) * 8;
            size_t gk = baseK + (size_t)(kb * 128 + row) * 64 + seg;
            size_t gv = baseV + (size_t)(kb * 128 + row) * 64 + seg;
            cp_async16(Kh + row * KSTR + seg, g_qhi + gk);
            cp_async16(Kl + row * KSTR + seg, g_qlo + gk);
            cp_async16(Vh + row * KSTR + seg, g_qhi + gv);
            cp_async16(Vl + row * KSTR + seg, g_qlo + gv);
        }
        cp_commit(); cp_wait0();
        __syncthreads();

        float L[4][4] = {};
        #pragma unroll
        for (int kk = 0; kk < 64; kk += 16) {
            uint32_t ah[4], al[4];
            ldsm4(ah, Qh + wm * 16 * QSTR + kk + offAQ);
            ldsm4(al, Ql + wm * 16 * QSTR + kk + offAQ);
            #pragma unroll
            for (int nt2 = 0; nt2 < 2; nt2++) {
                uint32_t tb[4], tc[4];
                ldsm4(tb, Kh + (wn * 32 + nt2 * 16) * KSTR + kk + offBK);
                ldsm4(tc, Kl + (wn * 32 + nt2 * 16) * KSTR + kk + offBK);
                uint32_t b0h[2] = { tb[0], tb[1] }, b1h[2] = { tb[2], tb[3] };
                uint32_t b0l[2] = { tc[0], tc[1] }, b1l[2] = { tc[2], tc[3] };
                mma_bf16(L[2*nt2],   ah, b0h);
                mma_bf16(L[2*nt2],   ah, b0l);
                mma_bf16(L[2*nt2],   al, b0h);
                mma_bf16(L[2*nt2+1], ah, b1h);
                mma_bf16(L[2*nt2+1], ah, b1l);
                mma_bf16(L[2*nt2+1], al, b1h);
            }
        }

        uint32_t pH0[4], pH1[4], pL0[4], pL1[4];
        const float* bsr = bs + (size_t)(wm * 16 + r0l) * 512 + kb * 128 + wn * 32 + c2;
        #pragma unroll
        for (int nt = 0; nt < 4; nt++) {
            float2 b0 = *reinterpret_cast<const float2*>(bsr + nt * 8);
            float2 b1 = *reinterpret_cast<const float2*>(bsr + nt * 8 + 8 * 512);
            float a0 = fmaf(L[nt][0], SCALE, b0.x);
            float a1 = fmaf(L[nt][1], SCALE, b0.y);
            float a2 = fmaf(L[nt][2], SCALE, b1.x);
            float a3 = fmaf(L[nt][3], SCALE, b1.y);
            if (a0 != 0.f || a1 != 0.f) nz0 = 1.f;
            if (a2 != 0.f || a3 != 0.f) nz1 = 1.f;
            float e0 = __expf(a0), e1 = __expf(a1), e2 = __expf(a2), e3 = __expf(a3);
            s0 += e0 + e1; s1 += e2 + e3;
            bf16 h0, l0, h1, l1;
            split2(e0, h0, l0); split2(e1, h1, l1);
            pH0[nt] = packhl(h0, h1); pL0[nt] = packhl(l0, l1);
            split2(e2, h0, l0); split2(e3, h1, l1);
            pH1[nt] = packhl(h0, h1); pL1[nt] = packhl(l0, l1);
        }

        #pragma unroll
        for (int kc = 0; kc < 2; kc++) {
            const int nt0 = kc * 2;
            uint32_t aH[4] = { pH0[nt0], pH1[nt0], pH0[nt0+1], pH1[nt0+1] };
            uint32_t aL[4] = { pL0[nt0], pL1[nt0], pL0[nt0+1], pL1[nt0+1] };
            const bf16* vb = Vh + (wn * 32 + kc * 16) * KSTR;
            const bf16* vc = Vl + (wn * 32 + kc * 16) * KSTR;
            #pragma unroll
            for (int dc = 0; dc < 4; dc++) {
                uint32_t tb[4], tc[4];
                ldsm4t(tb, vb + dc * 16 + offVt);
                ldsm4t(tc, vc + dc * 16 + offVt);
                uint32_t b0h[2] = { tb[0], tb[1] }, b1h[2] = { tb[2], tb[3] };
                uint32_t b0l[2] = { tc[0], tc[1] }, b1l[2] = { tc[2], tc[3] };
                mma_bf16(ao[dc*2],   aH, b0h);
                mma_bf16(ao[dc*2],   aH, b0l);
                mma_bf16(ao[dc*2],   aL, b0h);
                mma_bf16(ao[dc*2+1], aH, b1h);
                mma_bf16(ao[dc*2+1], aH, b1l);
                mma_bf16(ao[dc*2+1], aL, b1h);
            }
        }
    }

    s0 += __shfl_xor_sync(~0u, s0, 1); s0 += __shfl_xor_sync(~0u, s0, 2);
    s1 += __shfl_xor_sync(~0u, s1, 1); s1 += __shfl_xor_sync(~0u, s1, 2);
    nz0 += __shfl_xor_sync(~0u, nz0, 1); nz0 += __shfl_xor_sync(~0u, nz0, 2);
    nz1 += __shfl_xor_sync(~0u, nz1, 1); nz1 += __shfl_xor_sync(~0u, nz1, 2);

    __syncthreads();
    if ((lane & 3) == 0) {
        sred[warp * 16 + r0l] = s0;  sred[warp * 16 + r0l + 8] = s1;
        nzred[warp * 16 + r0l] = nz0; nzred[warp * 16 + r0l + 8] = nz1;
    }
    {
        float* op = opart + wn * 2048;
        int rr0 = wm * 16 + r0l;
        #pragma unroll
        for (int dc = 0; dc < 4; dc++)
            #pragma unroll
            for (int j = 0; j < 2; j++) {
                int col = dc * 16 + j * 8 + c2;
                *reinterpret_cast<float2*>(op + rr0 * 64 + col) =
                    make_float2(ao[dc*2+j][0], ao[dc*2+j][1]);
                *reinterpret_cast<float2*>(op + (rr0 + 8) * 64 + col) =
                    make_float2(ao[dc*2+j][2], ao[dc*2+j][3]);
            }
    }
    __syncthreads();

    {
        int row = tid >> 3, d0 = (tid & 7) * 8;
        int row16 = row & 15, wmr = row >> 4;
        float s = sred[(wmr*4+0)*16 + row16] + sred[(wmr*4+1)*16 + row16]
                + sred[(wmr*4+2)*16 + row16] + sred[(wmr*4+3)*16 + row16];
        float nzt = nzred[(wmr*4+0)*16 + row16] + nzred[(wmr*4+1)*16 + row16]
                  + nzred[(wmr*4+2)*16 + row16] + nzred[(wmr*4+3)*16 + row16];
        float inv = (nzt > 0.f) ? (1.f / s) : 0.f;
        __align__(16) bf16 hs[8], ls[8];
        #pragma unroll
        for (int j = 0; j < 8; j++) {
            float o = (opart[row * 64 + d0 + j] + opart[2048 + row * 64 + d0 + j]
                     + opart[4096 + row * 64 + d0 + j] + opart[6144 + row * 64 + d0 + j]) * inv;
            split2(o, hs[j], ls[j]);
        }
        int b = bh >> 4, h = bh & 15;
        size_t gidx = ((size_t)(b * 512 + rb * 32 + row)) * 1024 + h * 64 + d0;
        *reinterpret_cast<uint4*>(g_ohi + gidx) = *reinterpret_cast<uint4*>(hs);
        *reinterpret_cast<uint4*>(g_olo + gidx) = *reinterpret_cast<uint4*>(ls);
    }
}

extern "C" void kernel_launch(void* const* d_in, const int* in_sizes, int n_in,
                              void* d_out, int out_size) {
    const float* x  = (const float*)d_in[0];
    const float* sp = (const float*)d_in[1];
    const float* ed = (const float*)d_in[2];

    cudaFuncSetAttribute(gemm128, cudaFuncAttributeMaxDynamicSharedMemorySize, GEMM_SMEM);
    cudaFuncSetAttribute(attn_kernel, cudaFuncAttributeMaxDynamicSharedMemorySize, ATTN_SMEM);

    bf16 *xhi, *xlo;
    cudaGetSymbolAddress((void**)&xhi, g_xhi);
    cudaGetSymbolAddress((void**)&xlo, g_xlo);

    split_kernel<<<8192, 256>>>((const float4*)x, xhi, xlo, 2097152);
    split_w_kernel<<<dim3(1024, 4), 256>>>((const float4*)d_in[3], (const float4*)d_in[4],
                                           (const float4*)d_in[5], (const float4*)d_in[6]);
    biassum_kernel<<<4096, 256>>>((const float4*)sp, (const float4*)ed, 1048576);
    // QKV projections
    gemm128<<<dim3(8, 64, 3), 256, GEMM_SMEM>>>(0, nullptr);
    // fused attention (register-resident P)
    attn_kernel<<<dim3(256, 16), 256, ATTN_SMEM>>>();
    // output projection -> d_out (fp32)
    gemm128<<<dim3(8, 64, 1), 256, GEMM_SMEM>>>(1, (float*)d_out);
}

// round 16
// speedup vs baseline: 2.0729x; 1.0193x over previous
#include <cuda_runtime.h>
#include <cuda_bf16.h>
#include <cstdint>

using bf16 = __nv_bfloat16;

#define SCALE 0.03125f  // D^-0.5, D=1024

// ---- scratch (device globals; allocation is forbidden) ----
__device__ bf16 g_xhi[8388608], g_xlo[8388608];        // x split [8192][1024]
__device__ bf16 g_whi[4194304], g_wlo[4194304];        // Wq,Wk,Wv,Wo split
__device__ bf16 g_qhi[25165824], g_qlo[25165824];      // q,k,v in [bh][n][d]
__device__ bf16 g_ohi[8388608], g_olo[8388608];        // attention out [8192][1024]
__device__ float g_bsum[4194304];                      // spatial+edge [16][512][512]

__device__ __forceinline__ void cp_async16(void* dst, const void* src) {
    uint32_t d = (uint32_t)__cvta_generic_to_shared(dst);
    asm volatile("cp.async.cg.shared.global [%0], [%1], 16;" :: "r"(d), "l"(src));
}
__device__ __forceinline__ void cp_commit() { asm volatile("cp.async.commit_group;"); }
__device__ __forceinline__ void cp_wait0()  { asm volatile("cp.async.wait_group 0;"); }
__device__ __forceinline__ void cp_wait1()  { asm volatile("cp.async.wait_group 1;"); }

__device__ __forceinline__ void ldsm4(uint32_t r[4], const void* p) {
    uint32_t a = (uint32_t)__cvta_generic_to_shared(p);
    asm volatile("ldmatrix.sync.aligned.m8n8.x4.shared.b16 {%0,%1,%2,%3}, [%4];"
                 : "=r"(r[0]), "=r"(r[1]), "=r"(r[2]), "=r"(r[3]) : "r"(a));
}
__device__ __forceinline__ void ldsm4t(uint32_t r[4], const void* p) {
    uint32_t a = (uint32_t)__cvta_generic_to_shared(p);
    asm volatile("ldmatrix.sync.aligned.m8n8.x4.trans.shared.b16 {%0,%1,%2,%3}, [%4];"
                 : "=r"(r[0]), "=r"(r[1]), "=r"(r[2]), "=r"(r[3]) : "r"(a));
}
__device__ __forceinline__ void mma_bf16(float c[4], const uint32_t a[4], const uint32_t b[2]) {
    asm volatile(
        "mma.sync.aligned.m16n8k16.row.col.f32.bf16.bf16.f32 "
        "{%0,%1,%2,%3}, {%4,%5,%6,%7}, {%8,%9}, {%0,%1,%2,%3};"
        : "+f"(c[0]), "+f"(c[1]), "+f"(c[2]), "+f"(c[3])
        : "r"(a[0]), "r"(a[1]), "r"(a[2]), "r"(a[3]), "r"(b[0]), "r"(b[1]));
}
__device__ __forceinline__ void split2(float v, bf16& h, bf16& l) {
    h = __float2bfloat16(v);
    l = __float2bfloat16(v - __bfloat162float(h));
}
__device__ __forceinline__ uint32_t packhl(bf16 a, bf16 b) {
    __nv_bfloat162 t; t.x = a; t.y = b;
    return *reinterpret_cast<uint32_t*>(&t);
}

// ---- prep ----
__global__ void split_kernel(const float4* __restrict__ src, bf16* hi, bf16* lo, int n4) {
    int i = blockIdx.x * blockDim.x + threadIdx.x;
    if (i >= n4) return;
    float4 v = src[i];
    __nv_bfloat162 a, b, c, d;
    split2(v.x, a.x, c.x); split2(v.y, a.y, c.y);
    split2(v.z, b.x, d.x); split2(v.w, b.y, d.y);
    __nv_bfloat162* ph = reinterpret_cast<__nv_bfloat162*>(hi) + 2 * i;
    ph[0] = a; ph[1] = b;
    __nv_bfloat162* pl = reinterpret_cast<__nv_bfloat162*>(lo) + 2 * i;
    pl[0] = c; pl[1] = d;
}
__global__ void split_w_kernel(const float4* __restrict__ w0, const float4* __restrict__ w1,
                               const float4* __restrict__ w2, const float4* __restrict__ w3) {
    int y = blockIdx.y;
    const float4* src = (y == 0) ? w0 : (y == 1) ? w1 : (y == 2) ? w2 : w3;
    int i = blockIdx.x * blockDim.x + threadIdx.x;
    float4 v = src[i];
    __nv_bfloat162 a, b, c, d;
    split2(v.x, a.x, c.x); split2(v.y, a.y, c.y);
    split2(v.z, b.x, d.x); split2(v.w, b.y, d.y);
    size_t base = (size_t)y * 524288 + 2 * (size_t)i;
    __nv_bfloat162* ph = reinterpret_cast<__nv_bfloat162*>(g_whi) + base;
    ph[0] = a; ph[1] = b;
    __nv_bfloat162* pl = reinterpret_cast<__nv_bfloat162*>(g_wlo) + base;
    pl[0] = c; pl[1] = d;
}
__global__ void biassum_kernel(const float4* __restrict__ a, const float4* __restrict__ b, int n4) {
    int i = blockIdx.x * blockDim.x + threadIdx.x;
    if (i >= n4) return;
    float4 u = a[i], v = b[i];
    reinterpret_cast<float4*>(g_bsum)[i] =
        make_float4(u.x + v.x, u.y + v.y, u.z + v.z, u.w + v.w);
}

// ---- GEMM: C[M,N] = A[M,K] * W[N,K]^T, 128x128 CTA tile, 3-stage pipeline ----
#define STG 32768
#define GEMM_SMEM (3 * STG)

__device__ __forceinline__ void storeQKV(int z, int row, int col, float v0, float v1) {
    int b = row >> 9, n = row & 511, h = col >> 6, d = col & 63;
    size_t idx = (size_t)z * 8388608 + ((size_t)((b << 4) + h) * 512 + n) * 64 + d;
    __nv_bfloat162 hh, ll;
    split2(v0, hh.x, ll.x); split2(v1, hh.y, ll.y);
    *reinterpret_cast<__nv_bfloat162*>(g_qhi + idx) = hh;
    *reinterpret_cast<__nv_bfloat162*>(g_qlo + idx) = ll;
}

__global__ void __launch_bounds__(256, 2) gemm128(int mode, float* __restrict__ outF) {
    extern __shared__ char smc[];
    const int tid = threadIdx.x, lane = tid & 31, warp = tid >> 5;
    const int wm = warp >> 2, wn = warp & 3;
    const int tm = blockIdx.y, tn = blockIdx.x, z = blockIdx.z;
    const bf16* Ahi = mode ? g_ohi : g_xhi;
    const bf16* Alo = mode ? g_olo : g_xlo;
    const int widx = mode ? 3 : z;
    const bf16* Bh = g_whi + (size_t)widx * 1048576;
    const bf16* Bl = g_wlo + (size_t)widx * 1048576;

    float acc[4][4][4] = {};

    const int rA = lane & 15, sA = lane >> 4, xA = rA & 7;
    const int rB = ((lane >> 4) << 3) + (lane & 7), sB = (lane >> 3) & 1, xB = rB & 7;
    int offAh[2], offAl[2], offBh[2], offBl[2];
    #pragma unroll
    for (int c = 0; c < 2; c++) {
        offAh[c] = rA * 128 + (((c * 2 + sA)     ^ xA) << 4);
        offAl[c] = rA * 128 + (((c * 2 + sA + 4) ^ xA) << 4);
        offBh[c] = rB * 128 + (((c * 2 + sB)     ^ xB) << 4);
        offBl[c] = rB * 128 + (((c * 2 + sB + 4) ^ xB) << 4);
    }

    auto load_stage = [&](int st, int kt) {
        char* base = smc + st * STG;
        const int kOff = kt * 32;
        #pragma unroll
        for (int i = 0; i < 4; i++) {
            int s = tid + i * 256;
            int r = s >> 3, c8 = s & 7;
            const bf16* src = (c8 < 4 ? Ahi : Alo) +
                              (size_t)(tm * 128 + r) * 1024 + kOff + (c8 & 3) * 8;
            cp_async16(base + r * 128 + ((c8 ^ (r & 7)) << 4), src);
        }
        #pragma unroll
        for (int i = 0; i < 4; i++) {
            int s = tid + i * 256;
            int r = s >> 3, c8 = s & 7;
            const bf16* src = (c8 < 4 ? Bh : Bl) +
                              (size_t)(tn * 128 + r) * 1024 + kOff + (c8 & 3) * 8;
            cp_async16(base + 16384 + r * 128 + ((c8 ^ (r & 7)) << 4), src);
        }
        cp_commit();
    };

    load_stage(0, 0);
    load_stage(1, 1);
    int st = 0;
    for (int kt = 0; kt < 32; kt++) {
        if (kt + 1 < 32) cp_wait1(); else cp_wait0();
        __syncthreads();
        if (kt + 2 < 32) {
            int stL = st + 2; if (stL >= 3) stL -= 3;
            load_stage(stL, kt + 2);
        }
        const char* At = smc + st * STG;
        const char* Bt = At + 16384;
        #pragma unroll
        for (int c = 0; c < 2; c++) {
            uint32_t bh[4][2], bl[4][2];
            #pragma unroll
            for (int nt2 = 0; nt2 < 2; nt2++) {
                uint32_t t[4];
                ldsm4(t, Bt + (wn * 32 + nt2 * 16) * 128 + offBh[c]);
                bh[2*nt2][0] = t[0]; bh[2*nt2][1] = t[1];
                bh[2*nt2+1][0] = t[2]; bh[2*nt2+1][1] = t[3];
                ldsm4(t, Bt + (wn * 32 + nt2 * 16) * 128 + offBl[c]);
                bl[2*nt2][0] = t[0]; bl[2*nt2][1] = t[1];
                bl[2*nt2+1][0] = t[2]; bl[2*nt2+1][1] = t[3];
            }
            #pragma unroll
            for (int mt = 0; mt < 4; mt++) {
                uint32_t ah[4], al[4];
                ldsm4(ah, At + (wm * 64 + mt * 16) * 128 + offAh[c]);
                ldsm4(al, At + (wm * 64 + mt * 16) * 128 + offAl[c]);
                // term-major: consecutive MMAs hit different accumulators
                #pragma unroll
                for (int nt = 0; nt < 4; nt++) mma_bf16(acc[mt][nt], ah, bh[nt]);
                #pragma unroll
                for (int nt = 0; nt < 4; nt++) mma_bf16(acc[mt][nt], ah, bl[nt]);
                #pragma unroll
                for (int nt = 0; nt < 4; nt++) mma_bf16(acc[mt][nt], al, bh[nt]);
            }
        }
        if (++st == 3) st = 0;
    }
    #pragma unroll
    for (int mt = 0; mt < 4; mt++)
        #pragma unroll
        for (int nt = 0; nt < 4; nt++) {
            int r0 = tm * 128 + wm * 64 + mt * 16 + (lane >> 2);
            int cc = tn * 128 + wn * 32 + nt * 8 + (lane & 3) * 2;
            if (mode == 0) {
                storeQKV(z, r0, cc, acc[mt][nt][0], acc[mt][nt][1]);
                storeQKV(z, r0 + 8, cc, acc[mt][nt][2], acc[mt][nt][3]);
            } else {
                *reinterpret_cast<float2*>(outF + (size_t)r0 * 1024 + cc) =
                    make_float2(acc[mt][nt][0], acc[mt][nt][1]);
                *reinterpret_cast<float2*>(outF + (size_t)(r0 + 8) * 1024 + cc) =
                    make_float2(acc[mt][nt][2], acc[mt][nt][3]);
            }
        }
}

// ---- fused attention, register-resident P, K/V load overlap ----
#define QSTR 72
#define KSTR 72
#define A_OFF_QH 0
#define A_OFF_QL 4608
#define A_OFF_KH 9216
#define A_OFF_KL 27648
#define A_OFF_VH 46080
#define A_OFF_VL 64512
#define A_OFF_SRED 82944
#define A_OFF_NZ  83456
#define A_OFF_OP  9216
#define ATTN_SMEM 83968

__global__ void __launch_bounds__(256, 2) attn_kernel() {
    extern __shared__ char smc[];
    bf16* Qh = reinterpret_cast<bf16*>(smc + A_OFF_QH);
    bf16* Ql = reinterpret_cast<bf16*>(smc + A_OFF_QL);
    bf16* Kh = reinterpret_cast<bf16*>(smc + A_OFF_KH);
    bf16* Kl = reinterpret_cast<bf16*>(smc + A_OFF_KL);
    bf16* Vh = reinterpret_cast<bf16*>(smc + A_OFF_VH);
    bf16* Vl = reinterpret_cast<bf16*>(smc + A_OFF_VL);
    float* sred  = reinterpret_cast<float*>(smc + A_OFF_SRED);
    float* nzred = reinterpret_cast<float*>(smc + A_OFF_NZ);
    float* opart = reinterpret_cast<float*>(smc + A_OFF_OP);

    const int tid = threadIdx.x, lane = tid & 31, warp = tid >> 5;
    const int wm = warp >> 2, wn = warp & 3;
    const int bh = blockIdx.x, rb = blockIdx.y;
    const size_t baseQ = (size_t)bh * 32768 + (size_t)rb * 2048;
    const size_t baseK = 8388608u + (size_t)bh * 32768;
    const size_t baseV = 16777216u + (size_t)bh * 32768;

    const int offAQ = (lane & 15) * QSTR + (lane >> 4) * 8;
    const int offBK = (((lane >> 4) << 3) + (lane & 7)) * KSTR + ((lane >> 3) & 1) * 8;
    const int offVt = ((((lane >> 3) & 1) << 3) + (lane & 7)) * KSTR + (lane >> 4) * 8;
    const int r0l = lane >> 2, c2 = (lane & 3) * 2;

    auto issueK = [&](int kb) {
        #pragma unroll
        for (int i = 0; i < 4; i++) {
            int c = tid + i * 256;
            int row = c >> 3, seg = (c & 7) * 8;
            size_t gk = baseK + (size_t)(kb * 128 + row) * 64 + seg;
            cp_async16(Kh + row * KSTR + seg, g_qhi + gk);
            cp_async16(Kl + row * KSTR + seg, g_qlo + gk);
        }
        cp_commit();
    };
    auto issueV = [&](int kb) {
        #pragma unroll
        for (int i = 0; i < 4; i++) {
            int c = tid + i * 256;
            int row = c >> 3, seg = (c & 7) * 8;
            size_t gv = baseV + (size_t)(kb * 128 + row) * 64 + seg;
            cp_async16(Vh + row * KSTR + seg, g_qhi + gv);
            cp_async16(Vl + row * KSTR + seg, g_qlo + gv);
        }
        cp_commit();
    };

    {
        int row = tid >> 3, seg = (tid & 7) * 8;
        *reinterpret_cast<uint4*>(Qh + row * QSTR + seg) =
            *reinterpret_cast<const uint4*>(g_qhi + baseQ + row * 64 + seg);
        *reinterpret_cast<uint4*>(Ql + row * QSTR + seg) =
            *reinterpret_cast<const uint4*>(g_qlo + baseQ + row * 64 + seg);
    }
    const float* bs = g_bsum + ((size_t)(bh >> 4) * 512 + (size_t)rb * 32) * 512;

    float ao[8][4] = {};
    float s0 = 0.f, s1 = 0.f, nz0 = 0.f, nz1 = 0.f;

    issueK(0);
    issueV(0);

    for (int kb = 0; kb < 4; kb++) {
        cp_wait1();          // oldest pending (K_kb) done
        __syncthreads();

        // QK^T, term-major ordering
        float L[4][4] = {};
        #pragma unroll
        for (int kk = 0; kk < 64; kk += 16) {
            uint32_t ah[4], al[4];
            ldsm4(ah, Qh + wm * 16 * QSTR + kk + offAQ);
            ldsm4(al, Ql + wm * 16 * QSTR + kk + offAQ);
            uint32_t bhh[4][2], bll[4][2];
            #pragma unroll
            for (int nt2 = 0; nt2 < 2; nt2++) {
                uint32_t tb[4], tc[4];
                ldsm4(tb, Kh + (wn * 32 + nt2 * 16) * KSTR + kk + offBK);
                ldsm4(tc, Kl + (wn * 32 + nt2 * 16) * KSTR + kk + offBK);
                bhh[2*nt2][0] = tb[0]; bhh[2*nt2][1] = tb[1];
                bhh[2*nt2+1][0] = tb[2]; bhh[2*nt2+1][1] = tb[3];
                bll[2*nt2][0] = tc[0]; bll[2*nt2][1] = tc[1];
                bll[2*nt2+1][0] = tc[2]; bll[2*nt2+1][1] = tc[3];
            }
            #pragma unroll
            for (int nt = 0; nt < 4; nt++) mma_bf16(L[nt], ah, bhh[nt]);
            #pragma unroll
            for (int nt = 0; nt < 4; nt++) mma_bf16(L[nt], ah, bll[nt]);
            #pragma unroll
            for (int nt = 0; nt < 4; nt++) mma_bf16(L[nt], al, bhh[nt]);
        }
        __syncthreads();                 // all QK reads of K done
        if (kb + 1 < 4) issueK(kb + 1);  // overlaps softmax + PV

        // softmax pieces (registers)
        uint32_t pH0[4], pH1[4], pL0[4], pL1[4];
        const float* bsr = bs + (size_t)(wm * 16 + r0l) * 512 + kb * 128 + wn * 32 + c2;
        #pragma unroll
        for (int nt = 0; nt < 4; nt++) {
            float2 b0 = *reinterpret_cast<const float2*>(bsr + nt * 8);
            float2 b1 = *reinterpret_cast<const float2*>(bsr + nt * 8 + 8 * 512);
            float a0 = fmaf(L[nt][0], SCALE, b0.x);
            float a1 = fmaf(L[nt][1], SCALE, b0.y);
            float a2 = fmaf(L[nt][2], SCALE, b1.x);
            float a3 = fmaf(L[nt][3], SCALE, b1.y);
            if (a0 != 0.f || a1 != 0.f) nz0 = 1.f;
            if (a2 != 0.f || a3 != 0.f) nz1 = 1.f;
            float e0 = __expf(a0), e1 = __expf(a1), e2 = __expf(a2), e3 = __expf(a3);
            s0 += e0 + e1; s1 += e2 + e3;
            bf16 h0, l0, h1, l1;
            split2(e0, h0, l0); split2(e1, h1, l1);
            pH0[nt] = packhl(h0, h1); pL0[nt] = packhl(l0, l1);
            split2(e2, h0, l0); split2(e3, h1, l1);
            pH1[nt] = packhl(h0, h1); pL1[nt] = packhl(l0, l1);
        }

        if (kb + 1 < 4) cp_wait1(); else cp_wait0();   // V_kb done
        __syncthreads();

        // P·V, term-major
        #pragma unroll
        for (int kc = 0; kc < 2; kc++) {
            const int nt0 = kc * 2;
            uint32_t aH[4] = { pH0[nt0], pH1[nt0], pH0[nt0+1], pH1[nt0+1] };
            uint32_t aL[4] = { pL0[nt0], pL1[nt0], pL0[nt0+1], pL1[nt0+1] };
            const bf16* vb = Vh + (wn * 32 + kc * 16) * KSTR;
            const bf16* vc = Vl + (wn * 32 + kc * 16) * KSTR;
            uint32_t bhf[8][2], blf[8][2];
            #pragma unroll
            for (int dc = 0; dc < 4; dc++) {
                uint32_t tb[4], tc[4];
                ldsm4t(tb, vb + dc * 16 + offVt);
                ldsm4t(tc, vc + dc * 16 + offVt);
                bhf[dc*2][0] = tb[0]; bhf[dc*2][1] = tb[1];
                bhf[dc*2+1][0] = tb[2]; bhf[dc*2+1][1] = tb[3];
                blf[dc*2][0] = tc[0]; blf[dc*2][1] = tc[1];
                blf[dc*2+1][0] = tc[2]; blf[dc*2+1][1] = tc[3];
            }
            #pragma unroll
            for (int j = 0; j < 8; j++) mma_bf16(ao[j], aH, bhf[j]);
            #pragma unroll
            for (int j = 0; j < 8; j++) mma_bf16(ao[j], aH, blf[j]);
            #pragma unroll
            for (int j = 0; j < 8; j++) mma_bf16(ao[j], aL, bhf[j]);
        }
        __syncthreads();                 // all PV reads of V done
        if (kb + 1 < 4) issueV(kb + 1);  // overlaps next QK
    }

    s0 += __shfl_xor_sync(~0u, s0, 1); s0 += __shfl_xor_sync(~0u, s0, 2);
    s1 += __shfl_xor_sync(~0u, s1, 1); s1 += __shfl_xor_sync(~0u, s1, 2);
    nz0 += __shfl_xor_sync(~0u, nz0, 1); nz0 += __shfl_xor_sync(~0u, nz0, 2);
    nz1 += __shfl_xor_sync(~0u, nz1, 1); nz1 += __shfl_xor_sync(~0u, nz1, 2);

    __syncthreads();
    if ((lane & 3) == 0) {
        sred[warp * 16 + r0l] = s0;  sred[warp * 16 + r0l + 8] = s1;
        nzred[warp * 16 + r0l] = nz0; nzred[warp * 16 + r0l + 8] = nz1;
    }
    {
        float* op = opart + wn * 2048;
        int rr0 = wm * 16 + r0l;
        #pragma unroll
        for (int dc = 0; dc < 4; dc++)
            #pragma unroll
            for (int j = 0; j < 2; j++) {
                int col = dc * 16 + j * 8 + c2;
                *reinterpret_cast<float2*>(op + rr0 * 64 + col) =
                    make_float2(ao[dc*2+j][0], ao[dc*2+j][1]);
                *reinterpret_cast<float2*>(op + (rr0 + 8) * 64 + col) =
                    make_float2(ao[dc*2+j][2], ao[dc*2+j][3]);
            }
    }
    __syncthreads();

    {
        int row = tid >> 3, d0 = (tid & 7) * 8;
        int row16 = row & 15, wmr = row >> 4;
        float s = sred[(wmr*4+0)*16 + row16] + sred[(wmr*4+1)*16 + row16]
                + sred[(wmr*4+2)*16 + row16] + sred[(wmr*4+3)*16 + row16];
        float nzt = nzred[(wmr*4+0)*16 + row16] + nzred[(wmr*4+1)*16 + row16]
                  + nzred[(wmr*4+2)*16 + row16] + nzred[(wmr*4+3)*16 + row16];
        float inv = (nzt > 0.f) ? (1.f / s) : 0.f;
        __align__(16) bf16 hs[8], ls[8];
        #pragma unroll
        for (int j = 0; j < 8; j++) {
            float o = (opart[row * 64 + d0 + j] + opart[2048 + row * 64 + d0 + j]
                     + opart[4096 + row * 64 + d0 + j] + opart[6144 + row * 64 + d0 + j]) * inv;
            split2(o, hs[j], ls[j]);
        }
        int b = bh >> 4, h = bh & 15;
        size_t gidx = ((size_t)(b * 512 + rb * 32 + row)) * 1024 + h * 64 + d0;
        *reinterpret_cast<uint4*>(g_ohi + gidx) = *reinterpret_cast<uint4*>(hs);
        *reinterpret_cast<uint4*>(g_olo + gidx) = *reinterpret_cast<uint4*>(ls);
    }
}

extern "C" void kernel_launch(void* const* d_in, const int* in_sizes, int n_in,
                              void* d_out, int out_size) {
    const float* x  = (const float*)d_in[0];
    const float* sp = (const float*)d_in[1];
    const float* ed = (const float*)d_in[2];

    cudaFuncSetAttribute(gemm128, cudaFuncAttributeMaxDynamicSharedMemorySize, GEMM_SMEM);
    cudaFuncSetAttribute(attn_kernel, cudaFuncAttributeMaxDynamicSharedMemorySize, ATTN_SMEM);

    bf16 *xhi, *xlo;
    cudaGetSymbolAddress((void**)&xhi, g_xhi);
    cudaGetSymbolAddress((void**)&xlo, g_xlo);

    split_kernel<<<8192, 256>>>((const float4*)x, xhi, xlo, 2097152);
    split_w_kernel<<<dim3(1024, 4), 256>>>((const float4*)d_in[3], (const float4*)d_in[4],
                                           (const float4*)d_in[5], (const float4*)d_in[6]);
    biassum_kernel<<<4096, 256>>>((const float4*)sp, (const float4*)ed, 1048576);
    // QKV projections
    gemm128<<<dim3(8, 64, 3), 256, GEMM_SMEM>>>(0, nullptr);
    // fused attention
    attn_kernel<<<dim3(256, 16), 256, ATTN_SMEM>>>();
    // output projection -> d_out (fp32)
    gemm128<<<dim3(8, 64, 1), 256, GEMM_SMEM>>>(1, (float*)d_out);
}